// round 5
// baseline (speedup 1.0000x reference)
#include <cuda_runtime.h>
#include <cuda_bf16.h>
#include <cstdint>
#include <math.h>

// ===========================================================================
// StyleGAN2 block, convs via warp-level mma.sync (bf16 hi+lo split, 3 MMAs).
// R5: CTA tile 128oc x 256px, input rows staged once per ic-chunk (all 9 taps
// read shifted windows), weights in a 3-stage cp.async ring.
// Output: [rgb_out (8*3*64*64)] ++ [x (8*512*64*64)], fp32.
// ===========================================================================

#define Bn 8
#define Cn 512
#define HIN 32
#define PIX 4096                 // 64*64
#define XELEMS (Bn*Cn*PIX)
#define RGBELEMS (Bn*3*PIX)
#define PADHW 66                 // 64 + 2 halo
#define PADCELLS (PADHW*PADHW)   // 4356

// smem layout (bytes from aligned base)
#define I_PLANE 50688            // 396 cells * 128B
#define W_BASE  101376           // = 2*I_PLANE (1024-aligned)
#define W_STAGE 32768            // WH 16KB + WL 16KB
#define DSMEM   (W_BASE + 3*W_STAGE)   // 199680

// ---------------- device scratch (allocation-free rule) -------------------
__device__ __nv_bfloat16 g_xaH[(size_t)Bn*PADCELLS*Cn];
__device__ __nv_bfloat16 g_xaL[(size_t)Bn*PADCELLS*Cn];
__device__ __nv_bfloat16 g_xbH[(size_t)Bn*PADCELLS*Cn];
__device__ __nv_bfloat16 g_xbL[(size_t)Bn*PADCELLS*Cn];
__device__ __nv_bfloat16 g_wt0H[9*Cn*Cn], g_wt0L[9*Cn*Cn];
__device__ __nv_bfloat16 g_wt1H[9*Cn*Cn], g_wt1L[9*Cn*Cn];
__device__ float g_s0[Bn*Cn], g_s1[Bn*Cn], g_s2[Bn*Cn];
__device__ float g_d0[Bn*Cn], g_d1[Bn*Cn];
__device__ float g_wsq0[Cn*Cn], g_wsq1[Cn*Cn];

// ---------------- helpers --------------------------------------------------
__device__ __forceinline__ uint32_t smem_u32(const void* p) {
    uint32_t a;
    asm("{ .reg .u64 t; cvta.to.shared.u64 t, %1; cvt.u32.u64 %0, t; }"
        : "=r"(a) : "l"(p));
    return a;
}
__device__ __forceinline__ void ldsm_x4(uint32_t* r, uint32_t addr) {
    asm volatile("ldmatrix.sync.aligned.m8n8.x4.shared.b16 {%0,%1,%2,%3}, [%4];"
        : "=r"(r[0]), "=r"(r[1]), "=r"(r[2]), "=r"(r[3]) : "r"(addr));
}
__device__ __forceinline__ void mma_bf16(float* c, const uint32_t* a,
                                         const uint32_t* b) {
    asm volatile(
        "mma.sync.aligned.m16n8k16.row.col.f32.bf16.bf16.f32 "
        "{%0,%1,%2,%3},{%4,%5,%6,%7},{%8,%9},{%0,%1,%2,%3};"
        : "+f"(c[0]), "+f"(c[1]), "+f"(c[2]), "+f"(c[3])
        : "r"(a[0]), "r"(a[1]), "r"(a[2]), "r"(a[3]), "r"(b[0]), "r"(b[1]));
}
__device__ __forceinline__ void cp16(uint32_t dst, const void* src) {
    asm volatile("cp.async.cg.shared.global [%0], [%1], 16;"
        :: "r"(dst), "l"(src));
}
#define CP_COMMIT() asm volatile("cp.async.commit_group;" ::: "memory")
#define CP_WAIT1()  asm volatile("cp.async.wait_group 1;" ::: "memory")

// ---------------------------------------------------------------------------
// styles
// ---------------------------------------------------------------------------
__global__ void k_styles(const float* __restrict__ w,
                         const float* __restrict__ sW0, const float* __restrict__ sB0,
                         const float* __restrict__ sW1, const float* __restrict__ sB1,
                         const float* __restrict__ sW2, const float* __restrict__ sB2)
{
    int idx = blockIdx.x * blockDim.x + threadIdx.x;
    if (idx >= 3 * Bn * Cn) return;
    int which = idx / (Bn * Cn);
    int rem   = idx % (Bn * Cn);
    int b = rem / Cn, c = rem % Cn;
    const float* sW = (which == 0) ? sW0 : (which == 1) ? sW1 : sW2;
    const float* sB = (which == 0) ? sB0 : (which == 1) ? sB1 : sB2;
    const float* wr = w + b * Cn;
    const float* sr = sW + c * Cn;
    float acc = 0.f;
    #pragma unroll 8
    for (int k = 0; k < Cn; ++k) acc += wr[k] * sr[k];
    acc += sB[c];
    ((which == 0) ? g_s0 : (which == 1) ? g_s1 : g_s2)[b * Cn + c] = acc;
}

__global__ void k_wsq(const float* __restrict__ w0, const float* __restrict__ w1)
{
    int idx = blockIdx.x * blockDim.x + threadIdx.x;
    if (idx >= 2 * Cn * Cn) return;
    const float* W = (idx < Cn * Cn) ? w0 : w1;
    float* out     = (idx < Cn * Cn) ? g_wsq0 : g_wsq1;
    int e = idx & (Cn * Cn - 1);
    const float* p = W + (size_t)e * 9;
    float a = 0.f;
    #pragma unroll
    for (int t = 0; t < 9; ++t) a += p[t] * p[t];
    out[e] = a;
}

__global__ void k_demod()
{
    int idx = blockIdx.x * blockDim.x + threadIdx.x;
    if (idx >= 2 * Bn * Cn) return;
    int which = idx / (Bn * Cn);
    int rem   = idx % (Bn * Cn);
    int b = rem / Cn, o = rem % Cn;
    const float* wsq = which ? g_wsq1 : g_wsq0;
    const float* s   = which ? g_s1 : g_s0;
    const float* wr = wsq + o * Cn;
    const float* sr = s + b * Cn;
    float acc = 0.f;
    #pragma unroll 8
    for (int k = 0; k < Cn; ++k) { float sv = sr[k]; acc += wr[k] * sv * sv; }
    (which ? g_d1 : g_d0)[b * Cn + o] = rsqrtf(acc + 1e-8f);
}

// ---------------------------------------------------------------------------
// weight prep: W[o][i][tap] fp32 -> hi/lo bf16 planes [tap][oc][ic]
// ---------------------------------------------------------------------------
__global__ void k_wprep(const float* __restrict__ w0, const float* __restrict__ w1)
{
    int idx = blockIdx.x * blockDim.x + threadIdx.x;
    if (idx >= 2 * 9 * Cn * Cn) return;
    int layer = idx / (9 * Cn * Cn);
    int r = idx % (9 * Cn * Cn);
    int tap = r / (Cn * Cn);
    int rr = r % (Cn * Cn);
    int o = rr >> 9, i = rr & 511;
    const float* W = layer ? w1 : w0;
    float v = W[((size_t)o * Cn + i) * 9 + tap];
    __nv_bfloat16 h = __float2bfloat16(v);
    __nv_bfloat16 l = __float2bfloat16(v - __bfloat162float(h));
    size_t a = ((size_t)tap * Cn + o) * Cn + i;
    if (layer) { g_wt1H[a] = h; g_wt1L[a] = l; }
    else       { g_wt0H[a] = h; g_wt0L[a] = l; }
}

// ---------------------------------------------------------------------------
// zero the halo borders of the 4 activation planes (uint32 = 2 channels)
// ---------------------------------------------------------------------------
__global__ void k_zero()
{
    int idx = blockIdx.x * blockDim.x + threadIdx.x;
    if (idx >= Bn * 260 * 256) return;
    int c2 = idx & 255;
    int cell = (idx >> 8) % 260;
    int b = (idx >> 8) / 260;
    int y, x;
    if (cell < 66)       { y = 0;  x = cell; }
    else if (cell < 132) { y = 65; x = cell - 66; }
    else { int r = cell - 132; y = 1 + (r & 63); x = (r >> 6) ? 65 : 0; }
    size_t a = ((((size_t)b * PADHW + y) * PADHW + x) * Cn) / 2 + c2;
    ((uint32_t*)g_xaH)[a] = 0u;
    ((uint32_t*)g_xaL)[a] = 0u;
    ((uint32_t*)g_xbH)[a] = 0u;
    ((uint32_t*)g_xbL)[a] = 0u;
}

// ---------------------------------------------------------------------------
// upsample maps 2x bilinear, *s0, write padded HWC hi/lo planes
// ---------------------------------------------------------------------------
__global__ void __launch_bounds__(256) k_up(const float* __restrict__ maps)
{
    __shared__ uint32_t tile[64 * 65];
    int bx = blockIdx.x;
    int b = bx >> 6, y = bx & 63;
    int tid = threadIdx.x;

    int yl = (y - 1) >> 1, yu = yl + 1;
    float wyu = (y & 1) ? 0.25f : 0.75f;
    yl = max(yl, 0); yu = min(yu, HIN - 1);

    for (int c0 = 0; c0 < Cn; c0 += 64) {
        #pragma unroll
        for (int k = 0; k < 16; ++k) {
            int e = tid + (k << 8);
            int c = e >> 6, x = e & 63;
            int xl = (x - 1) >> 1, xu = xl + 1;
            float wxu = (x & 1) ? 0.25f : 0.75f;
            xl = max(xl, 0); xu = min(xu, HIN - 1);
            const float* p = maps + (size_t)(b * Cn + c0 + c) * (HIN * HIN);
            float v = (1.f - wyu) * ((1.f - wxu) * p[yl*HIN+xl] + wxu * p[yl*HIN+xu])
                    +         wyu * ((1.f - wxu) * p[yu*HIN+xl] + wxu * p[yu*HIN+xu]);
            v *= g_s0[b * Cn + c0 + c];
            __nv_bfloat16 h = __float2bfloat16(v);
            __nv_bfloat16 l = __float2bfloat16(v - __bfloat162float(h));
            tile[c * 65 + x] = ((uint32_t)__bfloat16_as_ushort(l) << 16) |
                               (uint32_t)__bfloat16_as_ushort(h);
        }
        __syncthreads();
        #pragma unroll
        for (int k = 0; k < 16; ++k) {
            int e = tid + (k << 8);
            int x = e >> 6, c = e & 63;
            uint32_t pk = tile[c * 65 + x];
            size_t a = (((size_t)b * PADHW + y + 1) * PADHW + x + 1) * Cn + c0 + c;
            g_xaH[a] = __ushort_as_bfloat16((unsigned short)(pk & 0xffff));
            g_xaL[a] = __ushort_as_bfloat16((unsigned short)(pk >> 16));
        }
        __syncthreads();
    }
}

// ---------------------------------------------------------------------------
// conv: CTA = 128 oc x 256 px (4 rows). 512 threads, warps 4(m) x 4(n);
// warp = 32 oc x 64 px (one full output row).
// Input rows staged once per ic-chunk (6 x 66 cells x 64 ic, hi+lo planes);
// weights (tap,ic) tiles in 3-stage cp.async ring.
// ---------------------------------------------------------------------------
__device__ __forceinline__ void stage_w(
    uint32_t wbase, int stg,
    const __nv_bfloat16* __restrict__ wH, const __nv_bfloat16* __restrict__ wL,
    int o0, int tap, int ic0, int tid)
{
    const uint32_t base = wbase + stg * W_STAGE;
    #pragma unroll
    for (int k = 0; k < 4; ++k) {
        int t = tid + (k << 9);
        int plane = t >> 10;                  // 0 = H, 1 = L
        int s = t & 1023;
        int r = s >> 3, g = s & 7;
        const __nv_bfloat16* src = (plane ? wL : wH)
            + ((size_t)tap * Cn + o0 + r) * Cn + ic0 + g * 8;
        uint32_t off = (uint32_t)((r << 7) + (g << 4));
        off ^= (off >> 3) & 0x70;
        cp16(base + plane * 16384 + off, src);
    }
}

__device__ __forceinline__ void stage_input(
    char* dbase,
    const __nv_bfloat16* __restrict__ xH, const __nv_bfloat16* __restrict__ xL,
    int b, int y0, int ic0, int tid)
{
    // 2 planes x 396 cells x 8 segs = 6336 16B segments
    for (int idx = tid; idx < 6336; idx += 512) {
        int plane = idx / 3168;
        int rem = idx - plane * 3168;
        int cell = rem >> 3, g = rem & 7;
        int r = cell / 66, x = cell - r * 66;
        const __nv_bfloat16* src = (plane ? xL : xH)
            + (((size_t)b * PADHW + y0 + r) * PADHW + x) * Cn + ic0 + g * 8;
        uint32_t off = (uint32_t)((cell << 7) + (g << 4));
        off ^= (off >> 3) & 0x70;
        *(uint4*)(dbase + plane * I_PLANE + off) = *(const uint4*)src;
    }
}

template<int EPI>
__global__ void __launch_bounds__(512) k_conv(
    const __nv_bfloat16* __restrict__ xH, const __nv_bfloat16* __restrict__ xL,
    const __nv_bfloat16* __restrict__ wH, const __nv_bfloat16* __restrict__ wL,
    const float* __restrict__ dmod,
    const float* __restrict__ bias,
    const float* __restrict__ nsc,
    const float* __restrict__ noise,
    const float* __restrict__ post,
    __nv_bfloat16* __restrict__ outH, __nv_bfloat16* __restrict__ outL,
    float* __restrict__ outF)
{
    extern __shared__ __align__(16) char dsm_raw[];
    char* dbase = (char*)(((uintptr_t)dsm_raw + 1023) & ~(uintptr_t)1023);
    const uint32_t ib = smem_u32(dbase);
    const uint32_t wbase = ib + W_BASE;
    const int tid = threadIdx.x;
    const int lane = tid & 31, wid = tid >> 5;
    const int mw = wid >> 2, nw = wid & 3;       // warp: 32oc x row nw
    const int b  = blockIdx.x >> 4;
    const int y0 = (blockIdx.x & 15) * 4;
    const int o0 = blockIdx.y * 128;

    float acc[2][8][4] = {};

    const int a_row = lane & 15;
    const int a_chalf = (lane >> 4) << 4;
    const int xl = ((lane >> 4) << 3) + (lane & 7);
    const int khalf = ((lane >> 3) & 1) << 4;

    stage_input(dbase, xH, xL, b, y0, 0, tid);
    stage_w(wbase, 0, wH, wL, o0, 0, 0, tid); CP_COMMIT();
    stage_w(wbase, 1, wH, wL, o0, 1, 0, tid); CP_COMMIT();

    int stg = 0, step = 0;
    for (int ic = 0; ic < 8; ++ic) {
        const int ic_next = (ic + 1) << 6;
        for (int tap = 0; tap < 9; ++tap, ++step) {
            CP_WAIT1();
            __syncthreads();
            int nstep = step + 2;
            if (nstep < 72)
                stage_w(wbase, (stg + 2) % 3, wH, wL, o0,
                        nstep % 9, (nstep / 9) << 6, tid);
            CP_COMMIT();

            const int ky = tap / 3, kx = tap - ky * 3;
            const int cellrow = (nw + ky) * 66 + kx;
            const uint32_t ws = wbase + stg * W_STAGE;

            #pragma unroll
            for (int ks = 0; ks < 4; ++ks) {
                uint32_t ah[2][4], al[2][4];
                #pragma unroll
                for (int sm = 0; sm < 2; ++sm) {
                    uint32_t off = (uint32_t)((mw*32 + sm*16 + a_row)*128 + ks*32 + a_chalf);
                    off ^= (off >> 3) & 0x70;
                    ldsm_x4(ah[sm], ws + off);
                    ldsm_x4(al[sm], ws + 16384 + off);
                }
                #pragma unroll
                for (int half = 0; half < 2; ++half) {
                    uint32_t bh[2][4], bl[2][4];
                    #pragma unroll
                    for (int sp = 0; sp < 2; ++sp) {
                        int x = (half * 2 + sp) * 16 + xl;
                        uint32_t off = (uint32_t)((cellrow + x)*128 + ks*32 + khalf);
                        off ^= (off >> 3) & 0x70;
                        ldsm_x4(bh[sp], ib + off);
                        ldsm_x4(bl[sp], ib + I_PLANE + off);
                    }
                    #pragma unroll
                    for (int sm = 0; sm < 2; ++sm)
                        #pragma unroll
                        for (int sp = 0; sp < 2; ++sp)
                            #pragma unroll
                            for (int j = 0; j < 2; ++j) {
                                float* a4 = acc[sm][half*4 + sp*2 + j];
                                mma_bf16(a4, ah[sm], &bh[sp][j*2]);
                                mma_bf16(a4, ah[sm], &bl[sp][j*2]);
                                mma_bf16(a4, al[sm], &bh[sp][j*2]);
                            }
                }
            }

            if (tap == 8 && ic < 7) {
                __syncthreads();
                stage_input(dbase, xH, xL, b, y0, ic_next, tid);
            }
            stg = (stg + 1) % 3;
        }
    }

    // ---- epilogue. c-frag: e0,e1=(row, col,col+1) e2,e3=(row+8, ..)
    const int groupM = lane >> 2;
    const int groupN = 2 * (lane & 3);
    const int yrow = y0 + nw;
    const float* np = noise + (size_t)b * PIX + yrow * 64;

    if (EPI == 0) {
        __syncthreads();
        uint32_t* tp = (uint32_t*)dbase;      // [256 px][132] (hi,lo) pairs
        #pragma unroll
        for (int sm = 0; sm < 2; ++sm) {
            #pragma unroll
            for (int ro = 0; ro < 2; ++ro) {
                int ocl = mw * 32 + sm * 16 + groupM + ro * 8;
                int oc = o0 + ocl;
                float d  = dmod[b * Cn + oc];
                float bi = bias[oc];
                float nv = nsc[oc];
                float ps = post[b * Cn + oc];
                #pragma unroll
                for (int sn = 0; sn < 8; ++sn) {
                    int x = sn * 8 + groupN;
                    #pragma unroll
                    for (int e = 0; e < 2; ++e) {
                        float v = acc[sm][sn][ro * 2 + e] * d + bi + nv * np[x + e];
                        v = (v >= 0.f) ? v : 0.2f * v;
                        v *= ps;
                        __nv_bfloat16 h = __float2bfloat16(v);
                        __nv_bfloat16 l = __float2bfloat16(v - __bfloat162float(h));
                        tp[(nw * 64 + x + e) * 132 + ocl] =
                            ((uint32_t)__bfloat16_as_ushort(l) << 16) |
                            (uint32_t)__bfloat16_as_ushort(h);
                    }
                }
            }
        }
        __syncthreads();
        int p = tid >> 1, q = tid & 1;
        int yy = y0 + (p >> 6), xx = p & 63;
        size_t abase = (((size_t)b * PADHW + yy + 1) * PADHW + xx + 1) * Cn + o0 + q * 64;
        uint4* dstH = (uint4*)(outH + abase);
        uint4* dstL = (uint4*)(outL + abase);
        const uint32_t* srcp = tp + p * 132 + q * 64;
        #pragma unroll
        for (int i = 0; i < 8; ++i) {
            uint32_t s0 = srcp[i*8+0], s1 = srcp[i*8+1], s2 = srcp[i*8+2], s3 = srcp[i*8+3];
            uint32_t s4 = srcp[i*8+4], s5 = srcp[i*8+5], s6 = srcp[i*8+6], s7 = srcp[i*8+7];
            dstH[i] = make_uint4(__byte_perm(s0,s1,0x5410), __byte_perm(s2,s3,0x5410),
                                 __byte_perm(s4,s5,0x5410), __byte_perm(s6,s7,0x5410));
            dstL[i] = make_uint4(__byte_perm(s0,s1,0x7632), __byte_perm(s2,s3,0x7632),
                                 __byte_perm(s4,s5,0x7632), __byte_perm(s6,s7,0x7632));
        }
    } else {
        #pragma unroll
        for (int sm = 0; sm < 2; ++sm) {
            #pragma unroll
            for (int ro = 0; ro < 2; ++ro) {
                int ocl = mw * 32 + sm * 16 + groupM + ro * 8;
                int oc = o0 + ocl;
                float d  = dmod[b * Cn + oc];
                float bi = bias[oc];
                float nv = nsc[oc];
                float* dst = outF + ((size_t)(b * Cn + oc) * 64 + yrow) * 64;
                #pragma unroll
                for (int sn = 0; sn < 8; ++sn) {
                    int x = sn * 8 + groupN;
                    float v0 = acc[sm][sn][ro * 2 + 0] * d + bi + nv * np[x + 0];
                    float v1 = acc[sm][sn][ro * 2 + 1] * d + bi + nv * np[x + 1];
                    v0 = (v0 >= 0.f) ? v0 : 0.2f * v0;
                    v1 = (v1 >= 0.f) ? v1 : 0.2f * v1;
                    *(float2*)(dst + x) = make_float2(v0, v1);
                }
            }
        }
    }
}

// ---------------------------------------------------------------------------
// to_rgb: rgb_out = up2(rgb) + rgbB + (rgbW*s2) . x
// ---------------------------------------------------------------------------
__global__ void __launch_bounds__(256) k_rgb(
    const float* __restrict__ x,
    const float* __restrict__ rgb,
    const float* __restrict__ rgbW,
    const float* __restrict__ rgbB,
    float* __restrict__ outRGB)
{
    __shared__ float ws[3 * Cn];
    int b    = blockIdx.x >> 4;
    int yblk = blockIdx.x & 15;
    int tid  = threadIdx.x;

    for (int idx = tid; idx < 3 * Cn; idx += 256)
        ws[idx] = rgbW[idx] * g_s2[b * Cn + (idx & (Cn - 1))];
    __syncthreads();

    int dy = tid >> 6;
    int X  = tid & 63;
    int Y  = yblk * 4 + dy;

    const float* xp = x + (size_t)b * Cn * PIX + Y * 64 + X;
    float a0 = 0.f, a1 = 0.f, a2 = 0.f;
    #pragma unroll 8
    for (int c = 0; c < Cn; ++c) {
        float v = xp[(size_t)c * PIX];
        a0 += ws[c] * v;
        a1 += ws[Cn + c] * v;
        a2 += ws[2 * Cn + c] * v;
    }

    int yl = (Y - 1) >> 1; int yu = yl + 1;
    float wyu = (Y & 1) ? 0.25f : 0.75f;
    yl = max(yl, 0); yu = min(yu, HIN - 1);
    int xl = (X - 1) >> 1; int xu = xl + 1;
    float wxu = (X & 1) ? 0.25f : 0.75f;
    xl = max(xl, 0); xu = min(xu, HIN - 1);

    float accs[3] = {a0, a1, a2};
    #pragma unroll
    for (int r = 0; r < 3; ++r) {
        const float* p = rgb + (size_t)(b * 3 + r) * (HIN * HIN);
        float up = (1.f - wyu) * ((1.f - wxu) * p[yl*HIN+xl] + wxu * p[yl*HIN+xu])
                 +         wyu * ((1.f - wxu) * p[yu*HIN+xl] + wxu * p[yu*HIN+xu]);
        outRGB[((size_t)(b * 3 + r) * 64 + Y) * 64 + X] = up + accs[r] + rgbB[r];
    }
}

// ---------------------------------------------------------------------------
extern "C" void kernel_launch(void* const* d_in, const int* in_sizes, int n_in,
                              void* d_out, int out_size)
{
    const float* maps   = (const float*)d_in[0];
    const float* w      = (const float*)d_in[1];
    const float* rgb    = (const float*)d_in[2];
    const float* noise0 = (const float*)d_in[3];
    const float* noise1 = (const float*)d_in[4];
    const float* w0     = (const float*)d_in[5];
    const float* b0     = (const float*)d_in[6];
    const float* sW0    = (const float*)d_in[7];
    const float* sB0    = (const float*)d_in[8];
    const float* ns0    = (const float*)d_in[9];
    const float* w1     = (const float*)d_in[10];
    const float* b1     = (const float*)d_in[11];
    const float* sW1    = (const float*)d_in[12];
    const float* sB1    = (const float*)d_in[13];
    const float* ns1    = (const float*)d_in[14];
    const float* rgbW   = (const float*)d_in[15];
    const float* rgbB   = (const float*)d_in[16];
    const float* rgbSW  = (const float*)d_in[17];
    const float* rgbSB  = (const float*)d_in[18];

    float* out    = (float*)d_out;
    float* outRGB = out;
    float* outX   = out + RGBELEMS;

    __nv_bfloat16 *xaH, *xaL, *xbH, *xbL, *wt0H, *wt0L, *wt1H, *wt1L;
    float *d0p, *d1p, *s1p;
    cudaGetSymbolAddress((void**)&xaH, g_xaH);
    cudaGetSymbolAddress((void**)&xaL, g_xaL);
    cudaGetSymbolAddress((void**)&xbH, g_xbH);
    cudaGetSymbolAddress((void**)&xbL, g_xbL);
    cudaGetSymbolAddress((void**)&wt0H, g_wt0H);
    cudaGetSymbolAddress((void**)&wt0L, g_wt0L);
    cudaGetSymbolAddress((void**)&wt1H, g_wt1H);
    cudaGetSymbolAddress((void**)&wt1L, g_wt1L);
    cudaGetSymbolAddress((void**)&d0p, g_d0);
    cudaGetSymbolAddress((void**)&d1p, g_d1);
    cudaGetSymbolAddress((void**)&s1p, g_s1);

    const int DSM = 1024 + DSMEM;
    cudaFuncSetAttribute(k_conv<0>, cudaFuncAttributeMaxDynamicSharedMemorySize, DSM);
    cudaFuncSetAttribute(k_conv<1>, cudaFuncAttributeMaxDynamicSharedMemorySize, DSM);

    k_styles<<<(3 * Bn * Cn + 255) / 256, 256>>>(w, sW0, sB0, sW1, sB1, rgbSW, rgbSB);
    k_wsq<<<(2 * Cn * Cn + 255) / 256, 256>>>(w0, w1);
    k_demod<<<(2 * Bn * Cn + 255) / 256, 256>>>();
    k_wprep<<<(2 * 9 * Cn * Cn + 255) / 256, 256>>>(w0, w1);
    k_zero<<<(Bn * 260 * 256 + 255) / 256, 256>>>();
    k_up<<<Bn * 64, 256>>>(maps);

    dim3 gconv(Bn * 16, 4);   // (b,ytile) x octile
    k_conv<0><<<gconv, 512, DSM>>>(xaH, xaL, wt0H, wt0L, d0p, b0, ns0, noise0,
                                   s1p, xbH, xbL, nullptr);
    k_conv<1><<<gconv, 512, DSM>>>(xbH, xbL, wt1H, wt1L, d1p, b1, ns1, noise1,
                                   nullptr, nullptr, nullptr, outX);

    k_rgb<<<Bn * 16, 256>>>(outX, rgb, rgbW, rgbB, outRGB);
}

// round 6
// speedup vs baseline: 1.1006x; 1.1006x over previous
#include <cuda_runtime.h>
#include <cuda_bf16.h>
#include <cstdint>
#include <math.h>

// ===========================================================================
// StyleGAN2 block, convs via warp-level mma.sync (bf16 hi+lo split, 3 MMAs).
// R6: R4 tile (128oc x 128px, acc=32 regs) + per-ic-chunk 4-row input band
// (all 9 taps read shifted windows; staged incrementally via cp.async),
// weights double-buffered via cp.async, B fragments via ldsm_x4.
// Output: [rgb_out (8*3*64*64)] ++ [x (8*512*64*64)], fp32.
// ===========================================================================

#define Bn 8
#define Cn 512
#define HIN 32
#define PIX 4096                 // 64*64
#define XELEMS (Bn*Cn*PIX)
#define RGBELEMS (Bn*3*PIX)
#define PADHW 66                 // 64 + 2 halo
#define PADCELLS (PADHW*PADHW)   // 4356

// smem layout (bytes from 1024-aligned base)
#define I_PLANE 33792            // 4 rows * 66 cells * 128B
#define I_BUF   67584            // 2 planes (H,L)
#define W_BASE  135168           // 2 input buffers
#define W_STAGE 32768            // WH 16KB + WL 16KB
#define DSMEM   (W_BASE + 2*W_STAGE)   // 200704

// ---------------- device scratch (allocation-free rule) -------------------
__device__ __nv_bfloat16 g_xaH[(size_t)Bn*PADCELLS*Cn];
__device__ __nv_bfloat16 g_xaL[(size_t)Bn*PADCELLS*Cn];
__device__ __nv_bfloat16 g_xbH[(size_t)Bn*PADCELLS*Cn];
__device__ __nv_bfloat16 g_xbL[(size_t)Bn*PADCELLS*Cn];
__device__ __nv_bfloat16 g_wt0H[9*Cn*Cn], g_wt0L[9*Cn*Cn];
__device__ __nv_bfloat16 g_wt1H[9*Cn*Cn], g_wt1L[9*Cn*Cn];
__device__ float g_s0[Bn*Cn], g_s1[Bn*Cn], g_s2[Bn*Cn];
__device__ float g_d0[Bn*Cn], g_d1[Bn*Cn];
__device__ float g_wsq0[Cn*Cn], g_wsq1[Cn*Cn];

// ---------------- helpers --------------------------------------------------
__device__ __forceinline__ uint32_t smem_u32(const void* p) {
    uint32_t a;
    asm("{ .reg .u64 t; cvta.to.shared.u64 t, %1; cvt.u32.u64 %0, t; }"
        : "=r"(a) : "l"(p));
    return a;
}
__device__ __forceinline__ void ldsm_x4(uint32_t* r, uint32_t addr) {
    asm volatile("ldmatrix.sync.aligned.m8n8.x4.shared.b16 {%0,%1,%2,%3}, [%4];"
        : "=r"(r[0]), "=r"(r[1]), "=r"(r[2]), "=r"(r[3]) : "r"(addr));
}
__device__ __forceinline__ void mma_bf16(float* c, const uint32_t* a,
                                         const uint32_t* b) {
    asm volatile(
        "mma.sync.aligned.m16n8k16.row.col.f32.bf16.bf16.f32 "
        "{%0,%1,%2,%3},{%4,%5,%6,%7},{%8,%9},{%0,%1,%2,%3};"
        : "+f"(c[0]), "+f"(c[1]), "+f"(c[2]), "+f"(c[3])
        : "r"(a[0]), "r"(a[1]), "r"(a[2]), "r"(a[3]), "r"(b[0]), "r"(b[1]));
}
__device__ __forceinline__ void cp16(uint32_t dst, const void* src) {
    asm volatile("cp.async.cg.shared.global [%0], [%1], 16;"
        :: "r"(dst), "l"(src));
}
#define CP_COMMIT() asm volatile("cp.async.commit_group;" ::: "memory")
#define CP_WAIT0()  asm volatile("cp.async.wait_group 0;" ::: "memory")

// ---------------------------------------------------------------------------
// styles
// ---------------------------------------------------------------------------
__global__ void k_styles(const float* __restrict__ w,
                         const float* __restrict__ sW0, const float* __restrict__ sB0,
                         const float* __restrict__ sW1, const float* __restrict__ sB1,
                         const float* __restrict__ sW2, const float* __restrict__ sB2)
{
    int idx = blockIdx.x * blockDim.x + threadIdx.x;
    if (idx >= 3 * Bn * Cn) return;
    int which = idx / (Bn * Cn);
    int rem   = idx % (Bn * Cn);
    int b = rem / Cn, c = rem % Cn;
    const float* sW = (which == 0) ? sW0 : (which == 1) ? sW1 : sW2;
    const float* sB = (which == 0) ? sB0 : (which == 1) ? sB1 : sB2;
    const float* wr = w + b * Cn;
    const float* sr = sW + c * Cn;
    float acc = 0.f;
    #pragma unroll 8
    for (int k = 0; k < Cn; ++k) acc += wr[k] * sr[k];
    acc += sB[c];
    ((which == 0) ? g_s0 : (which == 1) ? g_s1 : g_s2)[b * Cn + c] = acc;
}

__global__ void k_wsq(const float* __restrict__ w0, const float* __restrict__ w1)
{
    int idx = blockIdx.x * blockDim.x + threadIdx.x;
    if (idx >= 2 * Cn * Cn) return;
    const float* W = (idx < Cn * Cn) ? w0 : w1;
    float* out     = (idx < Cn * Cn) ? g_wsq0 : g_wsq1;
    int e = idx & (Cn * Cn - 1);
    const float* p = W + (size_t)e * 9;
    float a = 0.f;
    #pragma unroll
    for (int t = 0; t < 9; ++t) a += p[t] * p[t];
    out[e] = a;
}

__global__ void k_demod()
{
    int idx = blockIdx.x * blockDim.x + threadIdx.x;
    if (idx >= 2 * Bn * Cn) return;
    int which = idx / (Bn * Cn);
    int rem   = idx % (Bn * Cn);
    int b = rem / Cn, o = rem % Cn;
    const float* wsq = which ? g_wsq1 : g_wsq0;
    const float* s   = which ? g_s1 : g_s0;
    const float* wr = wsq + o * Cn;
    const float* sr = s + b * Cn;
    float acc = 0.f;
    #pragma unroll 8
    for (int k = 0; k < Cn; ++k) { float sv = sr[k]; acc += wr[k] * sv * sv; }
    (which ? g_d1 : g_d0)[b * Cn + o] = rsqrtf(acc + 1e-8f);
}

// ---------------------------------------------------------------------------
// weight prep: W[o][i][tap] fp32 -> hi/lo bf16 planes [tap][oc][ic]
// ---------------------------------------------------------------------------
__global__ void k_wprep(const float* __restrict__ w0, const float* __restrict__ w1)
{
    int idx = blockIdx.x * blockDim.x + threadIdx.x;
    if (idx >= 2 * 9 * Cn * Cn) return;
    int layer = idx / (9 * Cn * Cn);
    int r = idx % (9 * Cn * Cn);
    int tap = r / (Cn * Cn);
    int rr = r % (Cn * Cn);
    int o = rr >> 9, i = rr & 511;
    const float* W = layer ? w1 : w0;
    float v = W[((size_t)o * Cn + i) * 9 + tap];
    __nv_bfloat16 h = __float2bfloat16(v);
    __nv_bfloat16 l = __float2bfloat16(v - __bfloat162float(h));
    size_t a = ((size_t)tap * Cn + o) * Cn + i;
    if (layer) { g_wt1H[a] = h; g_wt1L[a] = l; }
    else       { g_wt0H[a] = h; g_wt0L[a] = l; }
}

// ---------------------------------------------------------------------------
// zero the halo borders of the 4 activation planes (uint32 = 2 channels)
// ---------------------------------------------------------------------------
__global__ void k_zero()
{
    int idx = blockIdx.x * blockDim.x + threadIdx.x;
    if (idx >= Bn * 260 * 256) return;
    int c2 = idx & 255;
    int cell = (idx >> 8) % 260;
    int b = (idx >> 8) / 260;
    int y, x;
    if (cell < 66)       { y = 0;  x = cell; }
    else if (cell < 132) { y = 65; x = cell - 66; }
    else { int r = cell - 132; y = 1 + (r & 63); x = (r >> 6) ? 65 : 0; }
    size_t a = ((((size_t)b * PADHW + y) * PADHW + x) * Cn) / 2 + c2;
    ((uint32_t*)g_xaH)[a] = 0u;
    ((uint32_t*)g_xaL)[a] = 0u;
    ((uint32_t*)g_xbH)[a] = 0u;
    ((uint32_t*)g_xbL)[a] = 0u;
}

// ---------------------------------------------------------------------------
// upsample maps 2x bilinear, *s0, write padded HWC hi/lo planes
// ---------------------------------------------------------------------------
__global__ void __launch_bounds__(256) k_up(const float* __restrict__ maps)
{
    __shared__ uint32_t tile[64 * 65];
    int bx = blockIdx.x;
    int b = bx >> 6, y = bx & 63;
    int tid = threadIdx.x;

    int yl = (y - 1) >> 1, yu = yl + 1;
    float wyu = (y & 1) ? 0.25f : 0.75f;
    yl = max(yl, 0); yu = min(yu, HIN - 1);

    for (int c0 = 0; c0 < Cn; c0 += 64) {
        #pragma unroll
        for (int k = 0; k < 16; ++k) {
            int e = tid + (k << 8);
            int c = e >> 6, x = e & 63;
            int xl = (x - 1) >> 1, xu = xl + 1;
            float wxu = (x & 1) ? 0.25f : 0.75f;
            xl = max(xl, 0); xu = min(xu, HIN - 1);
            const float* p = maps + (size_t)(b * Cn + c0 + c) * (HIN * HIN);
            float v = (1.f - wyu) * ((1.f - wxu) * p[yl*HIN+xl] + wxu * p[yl*HIN+xu])
                    +         wyu * ((1.f - wxu) * p[yu*HIN+xl] + wxu * p[yu*HIN+xu]);
            v *= g_s0[b * Cn + c0 + c];
            __nv_bfloat16 h = __float2bfloat16(v);
            __nv_bfloat16 l = __float2bfloat16(v - __bfloat162float(h));
            tile[c * 65 + x] = ((uint32_t)__bfloat16_as_ushort(l) << 16) |
                               (uint32_t)__bfloat16_as_ushort(h);
        }
        __syncthreads();
        #pragma unroll
        for (int k = 0; k < 16; ++k) {
            int e = tid + (k << 8);
            int x = e >> 6, c = e & 63;
            uint32_t pk = tile[c * 65 + x];
            size_t a = (((size_t)b * PADHW + y + 1) * PADHW + x + 1) * Cn + c0 + c;
            g_xaH[a] = __ushort_as_bfloat16((unsigned short)(pk & 0xffff));
            g_xaL[a] = __ushort_as_bfloat16((unsigned short)(pk >> 16));
        }
        __syncthreads();
    }
}

// ---------------------------------------------------------------------------
// conv staging
// ---------------------------------------------------------------------------
// weights: one (tap, 64ic) tile -> WH/WL (128oc x 128B), 2048 cp16 segs
__device__ __forceinline__ void stage_w(
    uint32_t wbase, int stg,
    const __nv_bfloat16* __restrict__ wH, const __nv_bfloat16* __restrict__ wL,
    int o0, int tap, int ic0, int tid)
{
    const uint32_t base = wbase + stg * W_STAGE;
    #pragma unroll
    for (int k = 0; k < 4; ++k) {
        int t = tid + (k << 9);
        int plane = t >> 10;
        int s = t & 1023;
        int r = s >> 3, g = s & 7;
        const __nv_bfloat16* src = (plane ? wL : wH)
            + ((size_t)tap * Cn + o0 + r) * Cn + ic0 + g * 8;
        uint32_t off = (uint32_t)((r << 7) + (g << 4));
        off ^= (off >> 3) & 0x70;
        cp16(base + plane * 16384 + off, src);
    }
}

// input band: 4 rows x 66 cells x 64 ic, hi+lo = 4224 cp16 segs, in 8 parts
__device__ __forceinline__ void stage_input_part(
    uint32_t ibase, int buf, int part,
    const __nv_bfloat16* __restrict__ xH, const __nv_bfloat16* __restrict__ xL,
    int b, int y0, int ic0, int tid)
{
    for (int t = tid; t < 528; t += 512) {
        int idx = part * 528 + t;
        int plane = idx / 2112;
        int rem = idx - plane * 2112;
        int cell = rem >> 3, g = rem & 7;
        int r = cell / 66, x = cell - r * 66;
        const __nv_bfloat16* src = (plane ? xL : xH)
            + (((size_t)b * PADHW + y0 + r) * PADHW + x) * Cn + ic0 + g * 8;
        uint32_t off = (uint32_t)((cell << 7) + (g << 4));
        off ^= (off >> 3) & 0x70;
        cp16(ibase + buf * I_BUF + plane * I_PLANE + off, src);
    }
}

// ---------------------------------------------------------------------------
// conv via mma.sync: D[128 oc, 128 px(2 rows)] over 8 ic-chunks x 9 taps,
// 3 MMAs per K=16 step. 512 threads, warps 4(m) x 4(n), warp 32oc x 32px.
// ---------------------------------------------------------------------------
template<int EPI>
__global__ void __launch_bounds__(512) k_conv(
    const __nv_bfloat16* __restrict__ xH, const __nv_bfloat16* __restrict__ xL,
    const __nv_bfloat16* __restrict__ wH, const __nv_bfloat16* __restrict__ wL,
    const float* __restrict__ dmod,
    const float* __restrict__ bias,
    const float* __restrict__ nsc,
    const float* __restrict__ noise,
    const float* __restrict__ post,
    __nv_bfloat16* __restrict__ outH, __nv_bfloat16* __restrict__ outL,
    float* __restrict__ outF)
{
    extern __shared__ __align__(16) char dsm_raw[];
    char* dbase = (char*)(((uintptr_t)dsm_raw + 1023) & ~(uintptr_t)1023);
    const uint32_t ib = smem_u32(dbase);
    const uint32_t wb = ib + W_BASE;
    const int tid = threadIdx.x;
    const int lane = tid & 31, wid = tid >> 5;
    const int mw = wid >> 2, nw = wid & 3;
    const int nt = blockIdx.x;
    const int o0 = blockIdx.y * 128;
    const int b  = nt >> 5;
    const int y0 = (nt & 31) * 2;

    float acc[2][4][4] = {};

    // fragment lane mappings
    const int a_row = lane & 15;
    const int a_chalf = (lane >> 4) << 4;
    const int xl = ((lane >> 4) << 3) + (lane & 7);   // px-in-16 for B x4
    const int khalf = ((lane >> 3) & 1) << 4;
    const int xbase = (nw & 1) * 32 + xl;             // column within row
    const int dyw = nw >> 1;                          // output row 0/1

    // prologue: full input band for chunk 0 + weights for step 0
    #pragma unroll
    for (int p = 0; p < 8; ++p)
        stage_input_part(ib, 0, p, xH, xL, b, y0, 0, tid);
    stage_w(wb, 0, wH, wL, o0, 0, 0, tid);
    CP_COMMIT();

    int step = 0;
    for (int ic = 0; ic < 8; ++ic) {
        const int ibuf = ic & 1;
        const uint32_t ibb = ib + ibuf * I_BUF;
        for (int tap = 0; tap < 9; ++tap, ++step) {
            CP_WAIT0();
            __syncthreads();
            // prefetch next step's weights + 1/8 of next chunk's input band
            int ns = step + 1;
            if (ns < 72)
                stage_w(wb, ns & 1, wH, wL, o0, ns % 9, (ns / 9) << 6, tid);
            if (tap < 8 && ic < 7)
                stage_input_part(ib, ibuf ^ 1, tap, xH, xL, b, y0,
                                 (ic + 1) << 6, tid);
            CP_COMMIT();

            const int ky = tap / 3, kx = tap - ky * 3;
            const int cellbase = (dyw + ky) * 66 + xbase + kx;
            const uint32_t ws = wb + (step & 1) * W_STAGE;

            #pragma unroll
            for (int ks = 0; ks < 4; ++ks) {
                uint32_t ah[2][4], al[2][4];
                #pragma unroll
                for (int sm = 0; sm < 2; ++sm) {
                    uint32_t off = (uint32_t)((mw*32 + sm*16 + a_row)*128
                                              + ks*32 + a_chalf);
                    off ^= (off >> 3) & 0x70;
                    ldsm_x4(ah[sm], ws + off);
                    ldsm_x4(al[sm], ws + 16384 + off);
                }
                #pragma unroll
                for (int half = 0; half < 2; ++half) {
                    uint32_t bh[4], bl[4];
                    uint32_t off = (uint32_t)((cellbase + half*16)*128
                                              + ks*32 + khalf);
                    off ^= (off >> 3) & 0x70;
                    ldsm_x4(bh, ibb + off);
                    ldsm_x4(bl, ibb + I_PLANE + off);
                    #pragma unroll
                    for (int sm = 0; sm < 2; ++sm)
                        #pragma unroll
                        for (int j = 0; j < 2; ++j) {
                            float* a4 = acc[sm][half*2 + j];
                            mma_bf16(a4, ah[sm], &bh[j*2]);
                            mma_bf16(a4, ah[sm], &bl[j*2]);
                            mma_bf16(a4, al[sm], &bh[j*2]);
                        }
                }
            }
        }
    }

    // ---- epilogue. c-frag: e0,e1=(row, col,col+1) e2,e3=(row+8, ..)
    const int groupM = lane >> 2;
    const int groupN = 2 * (lane & 3);
    const float* np = noise + (size_t)b * PIX + y0 * 64;

    if (EPI == 0) {
        __syncthreads();
        uint32_t* tp = (uint32_t*)dbase;      // [128 px][132] (hi,lo) pairs
        #pragma unroll
        for (int sm = 0; sm < 2; ++sm) {
            #pragma unroll
            for (int ro = 0; ro < 2; ++ro) {
                int ocl = mw * 32 + sm * 16 + groupM + ro * 8;
                int oc = o0 + ocl;
                float d  = dmod[b * Cn + oc];
                float bi = bias[oc];
                float nv = nsc[oc];
                float ps = post[b * Cn + oc];
                #pragma unroll
                for (int sn = 0; sn < 4; ++sn) {
                    int px = nw * 32 + sn * 8 + groupN;
                    #pragma unroll
                    for (int e = 0; e < 2; ++e) {
                        float v = acc[sm][sn][ro * 2 + e] * d + bi + nv * np[px + e];
                        v = (v >= 0.f) ? v : 0.2f * v;
                        v *= ps;
                        __nv_bfloat16 h = __float2bfloat16(v);
                        __nv_bfloat16 l = __float2bfloat16(v - __bfloat162float(h));
                        tp[(px + e) * 132 + ocl] =
                            ((uint32_t)__bfloat16_as_ushort(l) << 16) |
                            (uint32_t)__bfloat16_as_ushort(h);
                    }
                }
            }
        }
        __syncthreads();
        int p = tid >> 2, q = tid & 3;
        int yy = y0 + (p >> 6), xx = p & 63;
        size_t abase = (((size_t)b * PADHW + yy + 1) * PADHW + xx + 1) * Cn + o0 + q * 32;
        uint4* dstH = (uint4*)(outH + abase);
        uint4* dstL = (uint4*)(outL + abase);
        const uint32_t* srcp = tp + p * 132 + q * 32;
        #pragma unroll
        for (int i = 0; i < 4; ++i) {
            uint32_t s0 = srcp[i*8+0], s1 = srcp[i*8+1], s2 = srcp[i*8+2], s3 = srcp[i*8+3];
            uint32_t s4 = srcp[i*8+4], s5 = srcp[i*8+5], s6 = srcp[i*8+6], s7 = srcp[i*8+7];
            dstH[i] = make_uint4(__byte_perm(s0,s1,0x5410), __byte_perm(s2,s3,0x5410),
                                 __byte_perm(s4,s5,0x5410), __byte_perm(s6,s7,0x5410));
            dstL[i] = make_uint4(__byte_perm(s0,s1,0x7632), __byte_perm(s2,s3,0x7632),
                                 __byte_perm(s4,s5,0x7632), __byte_perm(s6,s7,0x7632));
        }
    } else {
        #pragma unroll
        for (int sm = 0; sm < 2; ++sm) {
            #pragma unroll
            for (int ro = 0; ro < 2; ++ro) {
                int ocl = mw * 32 + sm * 16 + groupM + ro * 8;
                int oc = o0 + ocl;
                float d  = dmod[b * Cn + oc];
                float bi = bias[oc];
                float nv = nsc[oc];
                #pragma unroll
                for (int sn = 0; sn < 4; ++sn) {
                    int px = nw * 32 + sn * 8 + groupN;
                    float v0 = acc[sm][sn][ro * 2 + 0] * d + bi + nv * np[px + 0];
                    float v1 = acc[sm][sn][ro * 2 + 1] * d + bi + nv * np[px + 1];
                    v0 = (v0 >= 0.f) ? v0 : 0.2f * v0;
                    v1 = (v1 >= 0.f) ? v1 : 0.2f * v1;
                    int y = y0 + (px >> 6), x = px & 63;
                    float2* dp = (float2*)(outF + ((size_t)(b * Cn + oc) * 64 + y) * 64 + x);
                    *dp = make_float2(v0, v1);
                }
            }
        }
    }
}

// ---------------------------------------------------------------------------
// to_rgb: rgb_out = up2(rgb) + rgbB + (rgbW*s2) . x
// ---------------------------------------------------------------------------
__global__ void __launch_bounds__(256) k_rgb(
    const float* __restrict__ x,
    const float* __restrict__ rgb,
    const float* __restrict__ rgbW,
    const float* __restrict__ rgbB,
    float* __restrict__ outRGB)
{
    __shared__ float ws[3 * Cn];
    int b    = blockIdx.x >> 4;
    int yblk = blockIdx.x & 15;
    int tid  = threadIdx.x;

    for (int idx = tid; idx < 3 * Cn; idx += 256)
        ws[idx] = rgbW[idx] * g_s2[b * Cn + (idx & (Cn - 1))];
    __syncthreads();

    int dy = tid >> 6;
    int X  = tid & 63;
    int Y  = yblk * 4 + dy;

    const float* xp = x + (size_t)b * Cn * PIX + Y * 64 + X;
    float a0 = 0.f, a1 = 0.f, a2 = 0.f;
    #pragma unroll 8
    for (int c = 0; c < Cn; ++c) {
        float v = xp[(size_t)c * PIX];
        a0 += ws[c] * v;
        a1 += ws[Cn + c] * v;
        a2 += ws[2 * Cn + c] * v;
    }

    int yl = (Y - 1) >> 1; int yu = yl + 1;
    float wyu = (Y & 1) ? 0.25f : 0.75f;
    yl = max(yl, 0); yu = min(yu, HIN - 1);
    int xl = (X - 1) >> 1; int xu = xl + 1;
    float wxu = (X & 1) ? 0.25f : 0.75f;
    xl = max(xl, 0); xu = min(xu, HIN - 1);

    float accs[3] = {a0, a1, a2};
    #pragma unroll
    for (int r = 0; r < 3; ++r) {
        const float* p = rgb + (size_t)(b * 3 + r) * (HIN * HIN);
        float up = (1.f - wyu) * ((1.f - wxu) * p[yl*HIN+xl] + wxu * p[yl*HIN+xu])
                 +         wyu * ((1.f - wxu) * p[yu*HIN+xl] + wxu * p[yu*HIN+xu]);
        outRGB[((size_t)(b * 3 + r) * 64 + Y) * 64 + X] = up + accs[r] + rgbB[r];
    }
}

// ---------------------------------------------------------------------------
extern "C" void kernel_launch(void* const* d_in, const int* in_sizes, int n_in,
                              void* d_out, int out_size)
{
    const float* maps   = (const float*)d_in[0];
    const float* w      = (const float*)d_in[1];
    const float* rgb    = (const float*)d_in[2];
    const float* noise0 = (const float*)d_in[3];
    const float* noise1 = (const float*)d_in[4];
    const float* w0     = (const float*)d_in[5];
    const float* b0     = (const float*)d_in[6];
    const float* sW0    = (const float*)d_in[7];
    const float* sB0    = (const float*)d_in[8];
    const float* ns0    = (const float*)d_in[9];
    const float* w1     = (const float*)d_in[10];
    const float* b1     = (const float*)d_in[11];
    const float* sW1    = (const float*)d_in[12];
    const float* sB1    = (const float*)d_in[13];
    const float* ns1    = (const float*)d_in[14];
    const float* rgbW   = (const float*)d_in[15];
    const float* rgbB   = (const float*)d_in[16];
    const float* rgbSW  = (const float*)d_in[17];
    const float* rgbSB  = (const float*)d_in[18];

    float* out    = (float*)d_out;
    float* outRGB = out;
    float* outX   = out + RGBELEMS;

    __nv_bfloat16 *xaH, *xaL, *xbH, *xbL, *wt0H, *wt0L, *wt1H, *wt1L;
    float *d0p, *d1p, *s1p;
    cudaGetSymbolAddress((void**)&xaH, g_xaH);
    cudaGetSymbolAddress((void**)&xaL, g_xaL);
    cudaGetSymbolAddress((void**)&xbH, g_xbH);
    cudaGetSymbolAddress((void**)&xbL, g_xbL);
    cudaGetSymbolAddress((void**)&wt0H, g_wt0H);
    cudaGetSymbolAddress((void**)&wt0L, g_wt0L);
    cudaGetSymbolAddress((void**)&wt1H, g_wt1H);
    cudaGetSymbolAddress((void**)&wt1L, g_wt1L);
    cudaGetSymbolAddress((void**)&d0p, g_d0);
    cudaGetSymbolAddress((void**)&d1p, g_d1);
    cudaGetSymbolAddress((void**)&s1p, g_s1);

    const int DSM = 1024 + DSMEM;
    cudaFuncSetAttribute(k_conv<0>, cudaFuncAttributeMaxDynamicSharedMemorySize, DSM);
    cudaFuncSetAttribute(k_conv<1>, cudaFuncAttributeMaxDynamicSharedMemorySize, DSM);

    k_styles<<<(3 * Bn * Cn + 255) / 256, 256>>>(w, sW0, sB0, sW1, sB1, rgbSW, rgbSB);
    k_wsq<<<(2 * Cn * Cn + 255) / 256, 256>>>(w0, w1);
    k_demod<<<(2 * Bn * Cn + 255) / 256, 256>>>();
    k_wprep<<<(2 * 9 * Cn * Cn + 255) / 256, 256>>>(w0, w1);
    k_zero<<<(Bn * 260 * 256 + 255) / 256, 256>>>();
    k_up<<<Bn * 64, 256>>>(maps);

    dim3 gconv(256, 4);
    k_conv<0><<<gconv, 512, DSM>>>(xaH, xaL, wt0H, wt0L, d0p, b0, ns0, noise0,
                                   s1p, xbH, xbL, nullptr);
    k_conv<1><<<gconv, 512, DSM>>>(xbH, xbL, wt1H, wt1L, d1p, b1, ns1, noise1,
                                   nullptr, nullptr, nullptr, outX);

    k_rgb<<<Bn * 16, 256>>>(outX, rgb, rgbW, rgbB, outRGB);
}

// round 7
// speedup vs baseline: 1.5970x; 1.4510x over previous
#include <cuda_runtime.h>
#include <cuda_fp16.h>
#include <cstdint>
#include <math.h>

// ===========================================================================
// StyleGAN2 block, convs via warp-level mma.sync fp16, asymmetric split:
// weights = wh + wl (fp16 pair), activations = single fp16 -> 2 MMAs/k-step.
// Output: [rgb_out (8*3*64*64)] ++ [x (8*512*64*64)], fp32.
// ===========================================================================

#define Bn 8
#define Cn 512
#define HIN 32
#define PIX 4096                 // 64*64
#define XELEMS (Bn*Cn*PIX)
#define RGBELEMS (Bn*3*PIX)
#define PADHW 66                 // 64 + 2 halo
#define PADCELLS (PADHW*PADHW)   // 4356

// smem layout (bytes from 1024-aligned base)
#define I_BUF   33792            // 4 rows * 66 cells * 128B (single fp16 plane)
#define W_BASE  67584            // 2 input buffers
#define W_STAGE 32768            // WH 16KB + WL 16KB
#define DSMEM   (W_BASE + 2*W_STAGE)   // 133120

// ---------------- device scratch (allocation-free rule) -------------------
__device__ __half g_xa[(size_t)Bn*PADCELLS*Cn];     // padded HWC fp16
__device__ __half g_xb[(size_t)Bn*PADCELLS*Cn];
__device__ __half g_wt0H[9*Cn*Cn], g_wt0L[9*Cn*Cn]; // [tap][oc][ic]
__device__ __half g_wt1H[9*Cn*Cn], g_wt1L[9*Cn*Cn];
__device__ float g_s0[Bn*Cn], g_s1[Bn*Cn], g_s2[Bn*Cn];
__device__ float g_d0[Bn*Cn], g_d1[Bn*Cn];
__device__ float g_wsq0[Cn*Cn], g_wsq1[Cn*Cn];

// ---------------- helpers --------------------------------------------------
__device__ __forceinline__ uint32_t smem_u32(const void* p) {
    uint32_t a;
    asm("{ .reg .u64 t; cvta.to.shared.u64 t, %1; cvt.u32.u64 %0, t; }"
        : "=r"(a) : "l"(p));
    return a;
}
__device__ __forceinline__ void ldsm_x4(uint32_t* r, uint32_t addr) {
    asm volatile("ldmatrix.sync.aligned.m8n8.x4.shared.b16 {%0,%1,%2,%3}, [%4];"
        : "=r"(r[0]), "=r"(r[1]), "=r"(r[2]), "=r"(r[3]) : "r"(addr));
}
__device__ __forceinline__ void mma_f16(float* c, const uint32_t* a,
                                        const uint32_t* b) {
    asm volatile(
        "mma.sync.aligned.m16n8k16.row.col.f32.f16.f16.f32 "
        "{%0,%1,%2,%3},{%4,%5,%6,%7},{%8,%9},{%0,%1,%2,%3};"
        : "+f"(c[0]), "+f"(c[1]), "+f"(c[2]), "+f"(c[3])
        : "r"(a[0]), "r"(a[1]), "r"(a[2]), "r"(a[3]), "r"(b[0]), "r"(b[1]));
}
__device__ __forceinline__ void cp16(uint32_t dst, const void* src) {
    asm volatile("cp.async.cg.shared.global [%0], [%1], 16;"
        :: "r"(dst), "l"(src));
}
#define CP_COMMIT() asm volatile("cp.async.commit_group;" ::: "memory")
#define CP_WAIT0()  asm volatile("cp.async.wait_group 0;" ::: "memory")

// ---------------------------------------------------------------------------
// styles
// ---------------------------------------------------------------------------
__global__ void k_styles(const float* __restrict__ w,
                         const float* __restrict__ sW0, const float* __restrict__ sB0,
                         const float* __restrict__ sW1, const float* __restrict__ sB1,
                         const float* __restrict__ sW2, const float* __restrict__ sB2)
{
    int idx = blockIdx.x * blockDim.x + threadIdx.x;
    if (idx >= 3 * Bn * Cn) return;
    int which = idx / (Bn * Cn);
    int rem   = idx % (Bn * Cn);
    int b = rem / Cn, c = rem % Cn;
    const float* sW = (which == 0) ? sW0 : (which == 1) ? sW1 : sW2;
    const float* sB = (which == 0) ? sB0 : (which == 1) ? sB1 : sB2;
    const float* wr = w + b * Cn;
    const float* sr = sW + c * Cn;
    float acc = 0.f;
    #pragma unroll 8
    for (int k = 0; k < Cn; ++k) acc += wr[k] * sr[k];
    acc += sB[c];
    ((which == 0) ? g_s0 : (which == 1) ? g_s1 : g_s2)[b * Cn + c] = acc;
}

__global__ void k_wsq(const float* __restrict__ w0, const float* __restrict__ w1)
{
    int idx = blockIdx.x * blockDim.x + threadIdx.x;
    if (idx >= 2 * Cn * Cn) return;
    const float* W = (idx < Cn * Cn) ? w0 : w1;
    float* out     = (idx < Cn * Cn) ? g_wsq0 : g_wsq1;
    int e = idx & (Cn * Cn - 1);
    const float* p = W + (size_t)e * 9;
    float a = 0.f;
    #pragma unroll
    for (int t = 0; t < 9; ++t) a += p[t] * p[t];
    out[e] = a;
}

__global__ void k_demod()
{
    int idx = blockIdx.x * blockDim.x + threadIdx.x;
    if (idx >= 2 * Bn * Cn) return;
    int which = idx / (Bn * Cn);
    int rem   = idx % (Bn * Cn);
    int b = rem / Cn, o = rem % Cn;
    const float* wsq = which ? g_wsq1 : g_wsq0;
    const float* s   = which ? g_s1 : g_s0;
    const float* wr = wsq + o * Cn;
    const float* sr = s + b * Cn;
    float acc = 0.f;
    #pragma unroll 8
    for (int k = 0; k < Cn; ++k) { float sv = sr[k]; acc += wr[k] * sv * sv; }
    (which ? g_d1 : g_d0)[b * Cn + o] = rsqrtf(acc + 1e-8f);
}

// ---------------------------------------------------------------------------
// weight prep: W[o][i][tap] fp32 -> fp16 hi/lo planes [tap][oc][ic]
// ---------------------------------------------------------------------------
__global__ void k_wprep(const float* __restrict__ w0, const float* __restrict__ w1)
{
    int idx = blockIdx.x * blockDim.x + threadIdx.x;
    if (idx >= 2 * 9 * Cn * Cn) return;
    int layer = idx / (9 * Cn * Cn);
    int r = idx % (9 * Cn * Cn);
    int tap = r / (Cn * Cn);
    int rr = r % (Cn * Cn);
    int o = rr >> 9, i = rr & 511;
    const float* W = layer ? w1 : w0;
    float v = W[((size_t)o * Cn + i) * 9 + tap];
    __half h = __float2half_rn(v);
    __half l = __float2half_rn(v - __half2float(h));
    size_t a = ((size_t)tap * Cn + o) * Cn + i;
    if (layer) { g_wt1H[a] = h; g_wt1L[a] = l; }
    else       { g_wt0H[a] = h; g_wt0L[a] = l; }
}

// ---------------------------------------------------------------------------
// zero the halo borders of the 2 activation planes (uint32 = 2 channels)
// ---------------------------------------------------------------------------
__global__ void k_zero()
{
    int idx = blockIdx.x * blockDim.x + threadIdx.x;
    if (idx >= Bn * 260 * 256) return;
    int c2 = idx & 255;
    int cell = (idx >> 8) % 260;
    int b = (idx >> 8) / 260;
    int y, x;
    if (cell < 66)       { y = 0;  x = cell; }
    else if (cell < 132) { y = 65; x = cell - 66; }
    else { int r = cell - 132; y = 1 + (r & 63); x = (r >> 6) ? 65 : 0; }
    size_t a = ((((size_t)b * PADHW + y) * PADHW + x) * Cn) / 2 + c2;
    ((uint32_t*)g_xa)[a] = 0u;
    ((uint32_t*)g_xb)[a] = 0u;
}

// ---------------------------------------------------------------------------
// upsample maps 2x bilinear, *s0, write padded HWC fp16 plane
// ---------------------------------------------------------------------------
__global__ void __launch_bounds__(256) k_up(const float* __restrict__ maps)
{
    __shared__ unsigned short tile[64 * 65];
    int bx = blockIdx.x;
    int b = bx >> 6, y = bx & 63;
    int tid = threadIdx.x;

    int yl = (y - 1) >> 1, yu = yl + 1;
    float wyu = (y & 1) ? 0.25f : 0.75f;
    yl = max(yl, 0); yu = min(yu, HIN - 1);

    for (int c0 = 0; c0 < Cn; c0 += 64) {
        #pragma unroll
        for (int k = 0; k < 16; ++k) {
            int e = tid + (k << 8);
            int c = e >> 6, x = e & 63;
            int xl = (x - 1) >> 1, xu = xl + 1;
            float wxu = (x & 1) ? 0.25f : 0.75f;
            xl = max(xl, 0); xu = min(xu, HIN - 1);
            const float* p = maps + (size_t)(b * Cn + c0 + c) * (HIN * HIN);
            float v = (1.f - wyu) * ((1.f - wxu) * p[yl*HIN+xl] + wxu * p[yl*HIN+xu])
                    +         wyu * ((1.f - wxu) * p[yu*HIN+xl] + wxu * p[yu*HIN+xu]);
            v *= g_s0[b * Cn + c0 + c];
            tile[c * 65 + x] = __half_as_ushort(__float2half_rn(v));
        }
        __syncthreads();
        #pragma unroll
        for (int k = 0; k < 16; ++k) {
            int e = tid + (k << 8);
            int x = e >> 6, c = e & 63;
            size_t a = (((size_t)b * PADHW + y + 1) * PADHW + x + 1) * Cn + c0 + c;
            g_xa[a] = __ushort_as_half(tile[c * 65 + x]);
        }
        __syncthreads();
    }
}

// ---------------------------------------------------------------------------
// conv staging
// ---------------------------------------------------------------------------
// weights: one (tap, 64ic) tile -> WH/WL (128oc x 128B), 2048 cp16 segs
__device__ __forceinline__ void stage_w(
    uint32_t wbase, int stg,
    const __half* __restrict__ wH, const __half* __restrict__ wL,
    int o0, int tap, int ic0, int tid)
{
    const uint32_t base = wbase + stg * W_STAGE;
    #pragma unroll
    for (int k = 0; k < 4; ++k) {
        int t = tid + (k << 9);
        int plane = t >> 10;
        int s = t & 1023;
        int r = s >> 3, g = s & 7;
        const __half* src = (plane ? wL : wH)
            + ((size_t)tap * Cn + o0 + r) * Cn + ic0 + g * 8;
        uint32_t off = (uint32_t)((r << 7) + (g << 4));
        off ^= (off >> 3) & 0x70;
        cp16(base + plane * 16384 + off, src);
    }
}

// input band: 4 rows x 66 cells x 64 ic fp16 = 2112 cp16 segs, in 8 parts
__device__ __forceinline__ void stage_input_part(
    uint32_t ibase, int buf, int part,
    const __half* __restrict__ x, int b, int y0, int ic0, int tid)
{
    if (tid < 264) {
        int idx = part * 264 + tid;
        int cell = idx >> 3, g = idx & 7;
        int r = cell / 66, xx = cell - r * 66;
        const __half* src = x
            + (((size_t)b * PADHW + y0 + r) * PADHW + xx) * Cn + ic0 + g * 8;
        uint32_t off = (uint32_t)((cell << 7) + (g << 4));
        off ^= (off >> 3) & 0x70;
        cp16(ibase + buf * I_BUF + off, src);
    }
}

// ---------------------------------------------------------------------------
// conv via mma.sync fp16: D[128 oc, 128 px(2 rows)] over 8 ic-chunks x 9 taps,
// 2 MMAs per K=16 step. 512 threads, warps 4(m) x 4(n), warp 32oc x 32px.
// ---------------------------------------------------------------------------
template<int EPI>
__global__ void __launch_bounds__(512) k_conv(
    const __half* __restrict__ xin,
    const __half* __restrict__ wH, const __half* __restrict__ wL,
    const float* __restrict__ dmod,
    const float* __restrict__ bias,
    const float* __restrict__ nsc,
    const float* __restrict__ noise,
    const float* __restrict__ post,
    __half* __restrict__ outHp,
    float* __restrict__ outF)
{
    extern __shared__ __align__(16) char dsm_raw[];
    char* dbase = (char*)(((uintptr_t)dsm_raw + 1023) & ~(uintptr_t)1023);
    const uint32_t ib = smem_u32(dbase);
    const uint32_t wb = ib + W_BASE;
    const int tid = threadIdx.x;
    const int lane = tid & 31, wid = tid >> 5;
    const int mw = wid >> 2, nw = wid & 3;
    const int nt = blockIdx.x;
    const int o0 = blockIdx.y * 128;
    const int b  = nt >> 5;
    const int y0 = (nt & 31) * 2;

    float acc[2][4][4] = {};

    // fragment lane mappings
    const int a_row = lane & 15;
    const int a_chalf = (lane >> 4) << 4;
    const int xl = ((lane >> 4) << 3) + (lane & 7);   // px-in-16 for B x4
    const int khalf = ((lane >> 3) & 1) << 4;
    const int xbase = (nw & 1) * 32 + xl;             // column within row
    const int dyw = nw >> 1;                          // output row 0/1

    // prologue: full input band for chunk 0 + weights for step 0
    #pragma unroll
    for (int p = 0; p < 8; ++p)
        stage_input_part(ib, 0, p, xin, b, y0, 0, tid);
    stage_w(wb, 0, wH, wL, o0, 0, 0, tid);
    CP_COMMIT();

    int step = 0;
    for (int ic = 0; ic < 8; ++ic) {
        const int ibuf = ic & 1;
        const uint32_t ibb = ib + ibuf * I_BUF;
        for (int tap = 0; tap < 9; ++tap, ++step) {
            CP_WAIT0();
            __syncthreads();
            int ns = step + 1;
            if (ns < 72)
                stage_w(wb, ns & 1, wH, wL, o0, ns % 9, (ns / 9) << 6, tid);
            if (tap < 8 && ic < 7)
                stage_input_part(ib, ibuf ^ 1, tap, xin, b, y0,
                                 (ic + 1) << 6, tid);
            CP_COMMIT();

            const int ky = tap / 3, kx = tap - ky * 3;
            const int cellbase = (dyw + ky) * 66 + xbase + kx;
            const uint32_t ws = wb + (step & 1) * W_STAGE;

            #pragma unroll
            for (int ks = 0; ks < 4; ++ks) {
                uint32_t ah[2][4], al[2][4];
                #pragma unroll
                for (int sm = 0; sm < 2; ++sm) {
                    uint32_t off = (uint32_t)((mw*32 + sm*16 + a_row)*128
                                              + ks*32 + a_chalf);
                    off ^= (off >> 3) & 0x70;
                    ldsm_x4(ah[sm], ws + off);
                    ldsm_x4(al[sm], ws + 16384 + off);
                }
                #pragma unroll
                for (int half = 0; half < 2; ++half) {
                    uint32_t bh[4];
                    uint32_t off = (uint32_t)((cellbase + half*16)*128
                                              + ks*32 + khalf);
                    off ^= (off >> 3) & 0x70;
                    ldsm_x4(bh, ibb + off);
                    #pragma unroll
                    for (int sm = 0; sm < 2; ++sm)
                        #pragma unroll
                        for (int j = 0; j < 2; ++j) {
                            float* a4 = acc[sm][half*2 + j];
                            mma_f16(a4, ah[sm], &bh[j*2]);
                            mma_f16(a4, al[sm], &bh[j*2]);
                        }
                }
            }
        }
    }

    // ---- epilogue. c-frag: e0,e1=(row, col,col+1) e2,e3=(row+8, ..)
    const int groupM = lane >> 2;
    const int groupN = 2 * (lane & 3);
    const float* np = noise + (size_t)b * PIX + y0 * 64;

    if (EPI == 0) {
        __syncthreads();
        uint32_t* tp = (uint32_t*)dbase;      // [64 px-pairs][132] u32
        #pragma unroll
        for (int sm = 0; sm < 2; ++sm) {
            #pragma unroll
            for (int ro = 0; ro < 2; ++ro) {
                int ocl = mw * 32 + sm * 16 + groupM + ro * 8;
                int oc = o0 + ocl;
                float d  = dmod[b * Cn + oc];
                float bi = bias[oc];
                float nv = nsc[oc];
                float ps = post[b * Cn + oc];
                #pragma unroll
                for (int sn = 0; sn < 4; ++sn) {
                    int px = nw * 32 + sn * 8 + groupN;
                    float v0 = acc[sm][sn][ro * 2 + 0] * d + bi + nv * np[px + 0];
                    float v1 = acc[sm][sn][ro * 2 + 1] * d + bi + nv * np[px + 1];
                    v0 = ((v0 >= 0.f) ? v0 : 0.2f * v0) * ps;
                    v1 = ((v1 >= 0.f) ? v1 : 0.2f * v1) * ps;
                    uint32_t pk = (uint32_t)__half_as_ushort(__float2half_rn(v0))
                        | ((uint32_t)__half_as_ushort(__float2half_rn(v1)) << 16);
                    tp[(px >> 1) * 132 + ocl] = pk;
                }
            }
        }
        __syncthreads();
        int p = tid >> 2, q = tid & 3;
        int yy = y0 + (p >> 6), xx = p & 63;
        uint32_t sel = (p & 1) ? 0x7632u : 0x5410u;
        size_t abase = (((size_t)b * PADHW + yy + 1) * PADHW + xx + 1) * Cn + o0 + q * 32;
        uint4* dst = (uint4*)(outHp + abase);
        const uint32_t* srcp = tp + (p >> 1) * 132 + q * 32;
        #pragma unroll
        for (int i = 0; i < 4; ++i) {
            dst[i] = make_uint4(
                __byte_perm(srcp[i*8+0], srcp[i*8+1], sel),
                __byte_perm(srcp[i*8+2], srcp[i*8+3], sel),
                __byte_perm(srcp[i*8+4], srcp[i*8+5], sel),
                __byte_perm(srcp[i*8+6], srcp[i*8+7], sel));
        }
    } else {
        #pragma unroll
        for (int sm = 0; sm < 2; ++sm) {
            #pragma unroll
            for (int ro = 0; ro < 2; ++ro) {
                int ocl = mw * 32 + sm * 16 + groupM + ro * 8;
                int oc = o0 + ocl;
                float d  = dmod[b * Cn + oc];
                float bi = bias[oc];
                float nv = nsc[oc];
                #pragma unroll
                for (int sn = 0; sn < 4; ++sn) {
                    int px = nw * 32 + sn * 8 + groupN;
                    float v0 = acc[sm][sn][ro * 2 + 0] * d + bi + nv * np[px + 0];
                    float v1 = acc[sm][sn][ro * 2 + 1] * d + bi + nv * np[px + 1];
                    v0 = (v0 >= 0.f) ? v0 : 0.2f * v0;
                    v1 = (v1 >= 0.f) ? v1 : 0.2f * v1;
                    int y = y0 + (px >> 6), x = px & 63;
                    float2* dp = (float2*)(outF + ((size_t)(b * Cn + oc) * 64 + y) * 64 + x);
                    *dp = make_float2(v0, v1);
                }
            }
        }
    }
}

// ---------------------------------------------------------------------------
// to_rgb: rgb_out = up2(rgb) + rgbB + (rgbW*s2) . x
// ---------------------------------------------------------------------------
__global__ void __launch_bounds__(256) k_rgb(
    const float* __restrict__ x,
    const float* __restrict__ rgb,
    const float* __restrict__ rgbW,
    const float* __restrict__ rgbB,
    float* __restrict__ outRGB)
{
    __shared__ float ws[3 * Cn];
    int b    = blockIdx.x >> 4;
    int yblk = blockIdx.x & 15;
    int tid  = threadIdx.x;

    for (int idx = tid; idx < 3 * Cn; idx += 256)
        ws[idx] = rgbW[idx] * g_s2[b * Cn + (idx & (Cn - 1))];
    __syncthreads();

    int dy = tid >> 6;
    int X  = tid & 63;
    int Y  = yblk * 4 + dy;

    const float* xp = x + (size_t)b * Cn * PIX + Y * 64 + X;
    float a0 = 0.f, a1 = 0.f, a2 = 0.f;
    #pragma unroll 8
    for (int c = 0; c < Cn; ++c) {
        float v = xp[(size_t)c * PIX];
        a0 += ws[c] * v;
        a1 += ws[Cn + c] * v;
        a2 += ws[2 * Cn + c] * v;
    }

    int yl = (Y - 1) >> 1; int yu = yl + 1;
    float wyu = (Y & 1) ? 0.25f : 0.75f;
    yl = max(yl, 0); yu = min(yu, HIN - 1);
    int xl = (X - 1) >> 1; int xu = xl + 1;
    float wxu = (X & 1) ? 0.25f : 0.75f;
    xl = max(xl, 0); xu = min(xu, HIN - 1);

    float accs[3] = {a0, a1, a2};
    #pragma unroll
    for (int r = 0; r < 3; ++r) {
        const float* p = rgb + (size_t)(b * 3 + r) * (HIN * HIN);
        float up = (1.f - wyu) * ((1.f - wxu) * p[yl*HIN+xl] + wxu * p[yl*HIN+xu])
                 +         wyu * ((1.f - wxu) * p[yu*HIN+xl] + wxu * p[yu*HIN+xu]);
        outRGB[((size_t)(b * 3 + r) * 64 + Y) * 64 + X] = up + accs[r] + rgbB[r];
    }
}

// ---------------------------------------------------------------------------
extern "C" void kernel_launch(void* const* d_in, const int* in_sizes, int n_in,
                              void* d_out, int out_size)
{
    const float* maps   = (const float*)d_in[0];
    const float* w      = (const float*)d_in[1];
    const float* rgb    = (const float*)d_in[2];
    const float* noise0 = (const float*)d_in[3];
    const float* noise1 = (const float*)d_in[4];
    const float* w0     = (const float*)d_in[5];
    const float* b0     = (const float*)d_in[6];
    const float* sW0    = (const float*)d_in[7];
    const float* sB0    = (const float*)d_in[8];
    const float* ns0    = (const float*)d_in[9];
    const float* w1     = (const float*)d_in[10];
    const float* b1     = (const float*)d_in[11];
    const float* sW1    = (const float*)d_in[12];
    const float* sB1    = (const float*)d_in[13];
    const float* ns1    = (const float*)d_in[14];
    const float* rgbW   = (const float*)d_in[15];
    const float* rgbB   = (const float*)d_in[16];
    const float* rgbSW  = (const float*)d_in[17];
    const float* rgbSB  = (const float*)d_in[18];

    float* out    = (float*)d_out;
    float* outRGB = out;
    float* outX   = out + RGBELEMS;

    __half *xa, *xb, *wt0H, *wt0L, *wt1H, *wt1L;
    float *d0p, *d1p, *s1p;
    cudaGetSymbolAddress((void**)&xa, g_xa);
    cudaGetSymbolAddress((void**)&xb, g_xb);
    cudaGetSymbolAddress((void**)&wt0H, g_wt0H);
    cudaGetSymbolAddress((void**)&wt0L, g_wt0L);
    cudaGetSymbolAddress((void**)&wt1H, g_wt1H);
    cudaGetSymbolAddress((void**)&wt1L, g_wt1L);
    cudaGetSymbolAddress((void**)&d0p, g_d0);
    cudaGetSymbolAddress((void**)&d1p, g_d1);
    cudaGetSymbolAddress((void**)&s1p, g_s1);

    const int DSM = 1024 + DSMEM;
    cudaFuncSetAttribute(k_conv<0>, cudaFuncAttributeMaxDynamicSharedMemorySize, DSM);
    cudaFuncSetAttribute(k_conv<1>, cudaFuncAttributeMaxDynamicSharedMemorySize, DSM);

    k_styles<<<(3 * Bn * Cn + 255) / 256, 256>>>(w, sW0, sB0, sW1, sB1, rgbSW, rgbSB);
    k_wsq<<<(2 * Cn * Cn + 255) / 256, 256>>>(w0, w1);
    k_demod<<<(2 * Bn * Cn + 255) / 256, 256>>>();
    k_wprep<<<(2 * 9 * Cn * Cn + 255) / 256, 256>>>(w0, w1);
    k_zero<<<(Bn * 260 * 256 + 255) / 256, 256>>>();
    k_up<<<Bn * 64, 256>>>(maps);

    dim3 gconv(256, 4);
    k_conv<0><<<gconv, 512, DSM>>>(xa, wt0H, wt0L, d0p, b0, ns0, noise0,
                                   s1p, xb, nullptr);
    k_conv<1><<<gconv, 512, DSM>>>(xb, wt1H, wt1L, d1p, b1, ns1, noise1,
                                   nullptr, nullptr, outX);

    k_rgb<<<Bn * 16, 256>>>(outX, rgb, rgbW, rgbB, outRGB);
}

// round 8
// speedup vs baseline: 2.3437x; 1.4676x over previous
#include <cuda_runtime.h>
#include <cuda_fp16.h>
#include <cstdint>
#include <math.h>

// ===========================================================================
// StyleGAN2 block, convs via warp-level mma.sync fp16 (single plane, 1 MMA
// per k-step). Weights fp16, activations fp16, fp32 accum.
// Output: [rgb_out (8*3*64*64)] ++ [x (8*512*64*64)], fp32.
// ===========================================================================

#define Bn 8
#define Cn 512
#define HIN 32
#define PIX 4096                 // 64*64
#define XELEMS (Bn*Cn*PIX)
#define RGBELEMS (Bn*3*PIX)
#define PADHW 66                 // 64 + 2 halo
#define PADCELLS (PADHW*PADHW)   // 4356

// smem layout (bytes from 1024-aligned base)
#define I_BUF   33792            // 4 rows * 66 cells * 128B (fp16)
#define W_BASE  67584            // 2 input buffers
#define W_STAGE 16384            // 128oc x 128B
#define DSMEM   (W_BASE + 2*W_STAGE)   // 100352

// ---------------- device scratch (allocation-free rule) -------------------
__device__ __half g_xa[(size_t)Bn*PADCELLS*Cn];     // padded HWC fp16
__device__ __half g_xb[(size_t)Bn*PADCELLS*Cn];
__device__ __half g_wt0[9*Cn*Cn];                   // [tap][oc][ic] fp16
__device__ __half g_wt1[9*Cn*Cn];
__device__ float g_s0[Bn*Cn], g_s1[Bn*Cn], g_s2[Bn*Cn];
__device__ float g_d0[Bn*Cn], g_d1[Bn*Cn];
__device__ float g_wsq0[Cn*Cn], g_wsq1[Cn*Cn];

// ---------------- helpers --------------------------------------------------
__device__ __forceinline__ uint32_t smem_u32(const void* p) {
    uint32_t a;
    asm("{ .reg .u64 t; cvta.to.shared.u64 t, %1; cvt.u32.u64 %0, t; }"
        : "=r"(a) : "l"(p));
    return a;
}
__device__ __forceinline__ void ldsm_x4(uint32_t* r, uint32_t addr) {
    asm volatile("ldmatrix.sync.aligned.m8n8.x4.shared.b16 {%0,%1,%2,%3}, [%4];"
        : "=r"(r[0]), "=r"(r[1]), "=r"(r[2]), "=r"(r[3]) : "r"(addr));
}
__device__ __forceinline__ void mma_f16(float* c, const uint32_t* a,
                                        const uint32_t* b) {
    asm volatile(
        "mma.sync.aligned.m16n8k16.row.col.f32.f16.f16.f32 "
        "{%0,%1,%2,%3},{%4,%5,%6,%7},{%8,%9},{%0,%1,%2,%3};"
        : "+f"(c[0]), "+f"(c[1]), "+f"(c[2]), "+f"(c[3])
        : "r"(a[0]), "r"(a[1]), "r"(a[2]), "r"(a[3]), "r"(b[0]), "r"(b[1]));
}
__device__ __forceinline__ void cp16(uint32_t dst, const void* src) {
    asm volatile("cp.async.cg.shared.global [%0], [%1], 16;"
        :: "r"(dst), "l"(src));
}
#define CP_COMMIT() asm volatile("cp.async.commit_group;" ::: "memory")
#define CP_WAIT0()  asm volatile("cp.async.wait_group 0;" ::: "memory")

// ---------------------------------------------------------------------------
// styles
// ---------------------------------------------------------------------------
__global__ void k_styles(const float* __restrict__ w,
                         const float* __restrict__ sW0, const float* __restrict__ sB0,
                         const float* __restrict__ sW1, const float* __restrict__ sB1,
                         const float* __restrict__ sW2, const float* __restrict__ sB2)
{
    int idx = blockIdx.x * blockDim.x + threadIdx.x;
    if (idx >= 3 * Bn * Cn) return;
    int which = idx / (Bn * Cn);
    int rem   = idx % (Bn * Cn);
    int b = rem / Cn, c = rem % Cn;
    const float* sW = (which == 0) ? sW0 : (which == 1) ? sW1 : sW2;
    const float* sB = (which == 0) ? sB0 : (which == 1) ? sB1 : sB2;
    const float* wr = w + b * Cn;
    const float* sr = sW + c * Cn;
    float acc = 0.f;
    #pragma unroll 8
    for (int k = 0; k < Cn; ++k) acc += wr[k] * sr[k];
    acc += sB[c];
    ((which == 0) ? g_s0 : (which == 1) ? g_s1 : g_s2)[b * Cn + c] = acc;
}

__global__ void k_wsq(const float* __restrict__ w0, const float* __restrict__ w1)
{
    int idx = blockIdx.x * blockDim.x + threadIdx.x;
    if (idx >= 2 * Cn * Cn) return;
    const float* W = (idx < Cn * Cn) ? w0 : w1;
    float* out     = (idx < Cn * Cn) ? g_wsq0 : g_wsq1;
    int e = idx & (Cn * Cn - 1);
    const float* p = W + (size_t)e * 9;
    float a = 0.f;
    #pragma unroll
    for (int t = 0; t < 9; ++t) a += p[t] * p[t];
    out[e] = a;
}

__global__ void k_demod()
{
    int idx = blockIdx.x * blockDim.x + threadIdx.x;
    if (idx >= 2 * Bn * Cn) return;
    int which = idx / (Bn * Cn);
    int rem   = idx % (Bn * Cn);
    int b = rem / Cn, o = rem % Cn;
    const float* wsq = which ? g_wsq1 : g_wsq0;
    const float* s   = which ? g_s1 : g_s0;
    const float* wr = wsq + o * Cn;
    const float* sr = s + b * Cn;
    float acc = 0.f;
    #pragma unroll 8
    for (int k = 0; k < Cn; ++k) { float sv = sr[k]; acc += wr[k] * sv * sv; }
    (which ? g_d1 : g_d0)[b * Cn + o] = rsqrtf(acc + 1e-8f);
}

// ---------------------------------------------------------------------------
// weight prep: W[o][i][tap] fp32 -> fp16 plane [tap][oc][ic]
// ---------------------------------------------------------------------------
__global__ void k_wprep(const float* __restrict__ w0, const float* __restrict__ w1)
{
    int idx = blockIdx.x * blockDim.x + threadIdx.x;
    if (idx >= 2 * 9 * Cn * Cn) return;
    int layer = idx / (9 * Cn * Cn);
    int r = idx % (9 * Cn * Cn);
    int tap = r / (Cn * Cn);
    int rr = r % (Cn * Cn);
    int o = rr >> 9, i = rr & 511;
    const float* W = layer ? w1 : w0;
    float v = W[((size_t)o * Cn + i) * 9 + tap];
    size_t a = ((size_t)tap * Cn + o) * Cn + i;
    (layer ? g_wt1 : g_wt0)[a] = __float2half_rn(v);
}

// ---------------------------------------------------------------------------
// zero the halo borders of the 2 activation planes (uint32 = 2 channels)
// ---------------------------------------------------------------------------
__global__ void k_zero()
{
    int idx = blockIdx.x * blockDim.x + threadIdx.x;
    if (idx >= Bn * 260 * 256) return;
    int c2 = idx & 255;
    int cell = (idx >> 8) % 260;
    int b = (idx >> 8) / 260;
    int y, x;
    if (cell < 66)       { y = 0;  x = cell; }
    else if (cell < 132) { y = 65; x = cell - 66; }
    else { int r = cell - 132; y = 1 + (r & 63); x = (r >> 6) ? 65 : 0; }
    size_t a = ((((size_t)b * PADHW + y) * PADHW + x) * Cn) / 2 + c2;
    ((uint32_t*)g_xa)[a] = 0u;
    ((uint32_t*)g_xb)[a] = 0u;
}

// ---------------------------------------------------------------------------
// upsample maps 2x bilinear, *s0, write padded HWC fp16 plane
// ---------------------------------------------------------------------------
__global__ void __launch_bounds__(256) k_up(const float* __restrict__ maps)
{
    __shared__ unsigned short tile[64 * 65];
    int bx = blockIdx.x;
    int b = bx >> 6, y = bx & 63;
    int tid = threadIdx.x;

    int yl = (y - 1) >> 1, yu = yl + 1;
    float wyu = (y & 1) ? 0.25f : 0.75f;
    yl = max(yl, 0); yu = min(yu, HIN - 1);

    for (int c0 = 0; c0 < Cn; c0 += 64) {
        #pragma unroll
        for (int k = 0; k < 16; ++k) {
            int e = tid + (k << 8);
            int c = e >> 6, x = e & 63;
            int xl = (x - 1) >> 1, xu = xl + 1;
            float wxu = (x & 1) ? 0.25f : 0.75f;
            xl = max(xl, 0); xu = min(xu, HIN - 1);
            const float* p = maps + (size_t)(b * Cn + c0 + c) * (HIN * HIN);
            float v = (1.f - wyu) * ((1.f - wxu) * p[yl*HIN+xl] + wxu * p[yl*HIN+xu])
                    +         wyu * ((1.f - wxu) * p[yu*HIN+xl] + wxu * p[yu*HIN+xu]);
            v *= g_s0[b * Cn + c0 + c];
            tile[c * 65 + x] = __half_as_ushort(__float2half_rn(v));
        }
        __syncthreads();
        #pragma unroll
        for (int k = 0; k < 16; ++k) {
            int e = tid + (k << 8);
            int x = e >> 6, c = e & 63;
            size_t a = (((size_t)b * PADHW + y + 1) * PADHW + x + 1) * Cn + c0 + c;
            g_xa[a] = __ushort_as_half(tile[c * 65 + x]);
        }
        __syncthreads();
    }
}

// ---------------------------------------------------------------------------
// conv staging
// ---------------------------------------------------------------------------
// weights: one (tap, 64ic) tile -> 128oc x 128B, 1024 cp16 segs
__device__ __forceinline__ void stage_w(
    uint32_t wbase, int stg, const __half* __restrict__ wp,
    int o0, int tap, int ic0, int tid)
{
    const uint32_t base = wbase + stg * W_STAGE;
    #pragma unroll
    for (int k = 0; k < 2; ++k) {
        int s = tid + (k << 9);
        int r = s >> 3, g = s & 7;
        const __half* src = wp + ((size_t)tap * Cn + o0 + r) * Cn + ic0 + g * 8;
        uint32_t off = (uint32_t)((r << 7) + (g << 4));
        off ^= (off >> 3) & 0x70;
        cp16(base + off, src);
    }
}

// input band: 4 rows x 66 cells x 64 ic fp16 = 2112 cp16 segs, in 8 parts
__device__ __forceinline__ void stage_input_part(
    uint32_t ibase, int buf, int part,
    const __half* __restrict__ x, int b, int y0, int ic0, int tid)
{
    if (tid < 264) {
        int idx = part * 264 + tid;
        int cell = idx >> 3, g = idx & 7;
        int r = cell / 66, xx = cell - r * 66;
        const __half* src = x
            + (((size_t)b * PADHW + y0 + r) * PADHW + xx) * Cn + ic0 + g * 8;
        uint32_t off = (uint32_t)((cell << 7) + (g << 4));
        off ^= (off >> 3) & 0x70;
        cp16(ibase + buf * I_BUF + off, src);
    }
}

// ---------------------------------------------------------------------------
// conv via mma.sync fp16: D[128 oc, 128 px(2 rows)] over 8 ic-chunks x 9 taps,
// 1 MMA per k-step. 512 threads, warps 4(m) x 4(n), warp 32oc x 32px.
// ---------------------------------------------------------------------------
template<int EPI>
__global__ void __launch_bounds__(512) k_conv(
    const __half* __restrict__ xin,
    const __half* __restrict__ wp,
    const float* __restrict__ dmod,
    const float* __restrict__ bias,
    const float* __restrict__ nsc,
    const float* __restrict__ noise,
    const float* __restrict__ post,
    __half* __restrict__ outHp,
    float* __restrict__ outF)
{
    extern __shared__ __align__(16) char dsm_raw[];
    char* dbase = (char*)(((uintptr_t)dsm_raw + 1023) & ~(uintptr_t)1023);
    const uint32_t ib = smem_u32(dbase);
    const uint32_t wb = ib + W_BASE;
    const int tid = threadIdx.x;
    const int lane = tid & 31, wid = tid >> 5;
    const int mw = wid >> 2, nw = wid & 3;
    const int nt = blockIdx.x;
    const int o0 = blockIdx.y * 128;
    const int b  = nt >> 5;
    const int y0 = (nt & 31) * 2;

    float acc[2][4][4] = {};

    // fragment lane mappings
    const int a_row = lane & 15;
    const int a_chalf = (lane >> 4) << 4;
    const int xl = ((lane >> 4) << 3) + (lane & 7);   // px-in-16 for B x4
    const int khalf = ((lane >> 3) & 1) << 4;
    const int xbase = (nw & 1) * 32 + xl;             // column within row
    const int dyw = nw >> 1;                          // output row 0/1

    // prologue: full input band for chunk 0 + weights for step 0
    #pragma unroll
    for (int p = 0; p < 8; ++p)
        stage_input_part(ib, 0, p, xin, b, y0, 0, tid);
    stage_w(wb, 0, wp, o0, 0, 0, tid);
    CP_COMMIT();

    int step = 0;
    for (int ic = 0; ic < 8; ++ic) {
        const int ibuf = ic & 1;
        const uint32_t ibb = ib + ibuf * I_BUF;
        for (int tap = 0; tap < 9; ++tap, ++step) {
            CP_WAIT0();
            __syncthreads();
            int ns = step + 1;
            if (ns < 72)
                stage_w(wb, ns & 1, wp, o0, ns % 9, (ns / 9) << 6, tid);
            if (tap < 8 && ic < 7)
                stage_input_part(ib, ibuf ^ 1, tap, xin, b, y0,
                                 (ic + 1) << 6, tid);
            CP_COMMIT();

            const int ky = tap / 3, kx = tap - ky * 3;
            const int cellbase = (dyw + ky) * 66 + xbase + kx;
            const uint32_t ws = wb + (step & 1) * W_STAGE;

            #pragma unroll
            for (int ks = 0; ks < 4; ++ks) {
                uint32_t ah[2][4];
                #pragma unroll
                for (int sm = 0; sm < 2; ++sm) {
                    uint32_t off = (uint32_t)((mw*32 + sm*16 + a_row)*128
                                              + ks*32 + a_chalf);
                    off ^= (off >> 3) & 0x70;
                    ldsm_x4(ah[sm], ws + off);
                }
                #pragma unroll
                for (int half = 0; half < 2; ++half) {
                    uint32_t bh[4];
                    uint32_t off = (uint32_t)((cellbase + half*16)*128
                                              + ks*32 + khalf);
                    off ^= (off >> 3) & 0x70;
                    ldsm_x4(bh, ibb + off);
                    #pragma unroll
                    for (int sm = 0; sm < 2; ++sm)
                        #pragma unroll
                        for (int j = 0; j < 2; ++j)
                            mma_f16(acc[sm][half*2 + j], ah[sm], &bh[j*2]);
                }
            }
        }
    }

    // ---- epilogue. c-frag: e0,e1=(row, col,col+1) e2,e3=(row+8, ..)
    const int groupM = lane >> 2;
    const int groupN = 2 * (lane & 3);
    const float* np = noise + (size_t)b * PIX + y0 * 64;

    if (EPI == 0) {
        __syncthreads();
        uint32_t* tp = (uint32_t*)dbase;      // [64 px-pairs][132] u32
        #pragma unroll
        for (int sm = 0; sm < 2; ++sm) {
            #pragma unroll
            for (int ro = 0; ro < 2; ++ro) {
                int ocl = mw * 32 + sm * 16 + groupM + ro * 8;
                int oc = o0 + ocl;
                float d  = dmod[b * Cn + oc];
                float bi = bias[oc];
                float nv = nsc[oc];
                float ps = post[b * Cn + oc];
                #pragma unroll
                for (int sn = 0; sn < 4; ++sn) {
                    int px = nw * 32 + sn * 8 + groupN;
                    float v0 = acc[sm][sn][ro * 2 + 0] * d + bi + nv * np[px + 0];
                    float v1 = acc[sm][sn][ro * 2 + 1] * d + bi + nv * np[px + 1];
                    v0 = ((v0 >= 0.f) ? v0 : 0.2f * v0) * ps;
                    v1 = ((v1 >= 0.f) ? v1 : 0.2f * v1) * ps;
                    uint32_t pk = (uint32_t)__half_as_ushort(__float2half_rn(v0))
                        | ((uint32_t)__half_as_ushort(__float2half_rn(v1)) << 16);
                    tp[(px >> 1) * 132 + ocl] = pk;
                }
            }
        }
        __syncthreads();
        int p = tid >> 2, q = tid & 3;
        int yy = y0 + (p >> 6), xx = p & 63;
        uint32_t sel = (p & 1) ? 0x7632u : 0x5410u;
        size_t abase = (((size_t)b * PADHW + yy + 1) * PADHW + xx + 1) * Cn + o0 + q * 32;
        uint4* dst = (uint4*)(outHp + abase);
        const uint32_t* srcp = tp + (p >> 1) * 132 + q * 32;
        #pragma unroll
        for (int i = 0; i < 4; ++i) {
            dst[i] = make_uint4(
                __byte_perm(srcp[i*8+0], srcp[i*8+1], sel),
                __byte_perm(srcp[i*8+2], srcp[i*8+3], sel),
                __byte_perm(srcp[i*8+4], srcp[i*8+5], sel),
                __byte_perm(srcp[i*8+6], srcp[i*8+7], sel));
        }
    } else {
        #pragma unroll
        for (int sm = 0; sm < 2; ++sm) {
            #pragma unroll
            for (int ro = 0; ro < 2; ++ro) {
                int ocl = mw * 32 + sm * 16 + groupM + ro * 8;
                int oc = o0 + ocl;
                float d  = dmod[b * Cn + oc];
                float bi = bias[oc];
                float nv = nsc[oc];
                #pragma unroll
                for (int sn = 0; sn < 4; ++sn) {
                    int px = nw * 32 + sn * 8 + groupN;
                    float v0 = acc[sm][sn][ro * 2 + 0] * d + bi + nv * np[px + 0];
                    float v1 = acc[sm][sn][ro * 2 + 1] * d + bi + nv * np[px + 1];
                    v0 = (v0 >= 0.f) ? v0 : 0.2f * v0;
                    v1 = (v1 >= 0.f) ? v1 : 0.2f * v1;
                    int y = y0 + (px >> 6), x = px & 63;
                    float2* dp = (float2*)(outF + ((size_t)(b * Cn + oc) * 64 + y) * 64 + x);
                    *dp = make_float2(v0, v1);
                }
            }
        }
    }
}

// ---------------------------------------------------------------------------
// to_rgb: rgb_out = up2(rgb) + rgbB + (rgbW*s2) . x
// ---------------------------------------------------------------------------
__global__ void __launch_bounds__(256) k_rgb(
    const float* __restrict__ x,
    const float* __restrict__ rgb,
    const float* __restrict__ rgbW,
    const float* __restrict__ rgbB,
    float* __restrict__ outRGB)
{
    __shared__ float ws[3 * Cn];
    int b    = blockIdx.x >> 4;
    int yblk = blockIdx.x & 15;
    int tid  = threadIdx.x;

    for (int idx = tid; idx < 3 * Cn; idx += 256)
        ws[idx] = rgbW[idx] * g_s2[b * Cn + (idx & (Cn - 1))];
    __syncthreads();

    int dy = tid >> 6;
    int X  = tid & 63;
    int Y  = yblk * 4 + dy;

    const float* xp = x + (size_t)b * Cn * PIX + Y * 64 + X;
    float a0 = 0.f, a1 = 0.f, a2 = 0.f;
    #pragma unroll 8
    for (int c = 0; c < Cn; ++c) {
        float v = xp[(size_t)c * PIX];
        a0 += ws[c] * v;
        a1 += ws[Cn + c] * v;
        a2 += ws[2 * Cn + c] * v;
    }

    int yl = (Y - 1) >> 1; int yu = yl + 1;
    float wyu = (Y & 1) ? 0.25f : 0.75f;
    yl = max(yl, 0); yu = min(yu, HIN - 1);
    int xl = (X - 1) >> 1; int xu = xl + 1;
    float wxu = (X & 1) ? 0.25f : 0.75f;
    xl = max(xl, 0); xu = min(xu, HIN - 1);

    float accs[3] = {a0, a1, a2};
    #pragma unroll
    for (int r = 0; r < 3; ++r) {
        const float* p = rgb + (size_t)(b * 3 + r) * (HIN * HIN);
        float up = (1.f - wyu) * ((1.f - wxu) * p[yl*HIN+xl] + wxu * p[yl*HIN+xu])
                 +         wyu * ((1.f - wxu) * p[yu*HIN+xl] + wxu * p[yu*HIN+xu]);
        outRGB[((size_t)(b * 3 + r) * 64 + Y) * 64 + X] = up + accs[r] + rgbB[r];
    }
}

// ---------------------------------------------------------------------------
extern "C" void kernel_launch(void* const* d_in, const int* in_sizes, int n_in,
                              void* d_out, int out_size)
{
    const float* maps   = (const float*)d_in[0];
    const float* w      = (const float*)d_in[1];
    const float* rgb    = (const float*)d_in[2];
    const float* noise0 = (const float*)d_in[3];
    const float* noise1 = (const float*)d_in[4];
    const float* w0     = (const float*)d_in[5];
    const float* b0     = (const float*)d_in[6];
    const float* sW0    = (const float*)d_in[7];
    const float* sB0    = (const float*)d_in[8];
    const float* ns0    = (const float*)d_in[9];
    const float* w1     = (const float*)d_in[10];
    const float* b1     = (const float*)d_in[11];
    const float* sW1    = (const float*)d_in[12];
    const float* sB1    = (const float*)d_in[13];
    const float* ns1    = (const float*)d_in[14];
    const float* rgbW   = (const float*)d_in[15];
    const float* rgbB   = (const float*)d_in[16];
    const float* rgbSW  = (const float*)d_in[17];
    const float* rgbSB  = (const float*)d_in[18];

    float* out    = (float*)d_out;
    float* outRGB = out;
    float* outX   = out + RGBELEMS;

    __half *xa, *xb, *wt0, *wt1;
    float *d0p, *d1p, *s1p;
    cudaGetSymbolAddress((void**)&xa, g_xa);
    cudaGetSymbolAddress((void**)&xb, g_xb);
    cudaGetSymbolAddress((void**)&wt0, g_wt0);
    cudaGetSymbolAddress((void**)&wt1, g_wt1);
    cudaGetSymbolAddress((void**)&d0p, g_d0);
    cudaGetSymbolAddress((void**)&d1p, g_d1);
    cudaGetSymbolAddress((void**)&s1p, g_s1);

    const int DSM = 1024 + DSMEM;
    cudaFuncSetAttribute(k_conv<0>, cudaFuncAttributeMaxDynamicSharedMemorySize, DSM);
    cudaFuncSetAttribute(k_conv<1>, cudaFuncAttributeMaxDynamicSharedMemorySize, DSM);

    k_styles<<<(3 * Bn * Cn + 255) / 256, 256>>>(w, sW0, sB0, sW1, sB1, rgbSW, rgbSB);
    k_wsq<<<(2 * Cn * Cn + 255) / 256, 256>>>(w0, w1);
    k_demod<<<(2 * Bn * Cn + 255) / 256, 256>>>();
    k_wprep<<<(2 * 9 * Cn * Cn + 255) / 256, 256>>>(w0, w1);
    k_zero<<<(Bn * 260 * 256 + 255) / 256, 256>>>();
    k_up<<<Bn * 64, 256>>>(maps);

    dim3 gconv(256, 4);
    k_conv<0><<<gconv, 512, DSM>>>(xa, wt0, d0p, b0, ns0, noise0,
                                   s1p, xb, nullptr);
    k_conv<1><<<gconv, 512, DSM>>>(xb, wt1, d1p, b1, ns1, noise1,
                                   nullptr, nullptr, outX);

    k_rgb<<<Bn * 16, 256>>>(outX, rgb, rgbW, rgbB, outRGB);
}

// round 9
// speedup vs baseline: 2.6288x; 1.1216x over previous
#include <cuda_runtime.h>
#include <cuda_fp16.h>
#include <cstdint>
#include <math.h>

// ===========================================================================
// StyleGAN2 block, convs via warp-level mma.sync fp16 (1 MMA/k-step).
// R9: 64oc x 128px CTAs (2048 CTAs, ~1% tail), 3-stage weight ring with
// cp.async.wait_group 1, fused prep kernels, parallel k_rgb.
// Output: [rgb_out (8*3*64*64)] ++ [x (8*512*64*64)], fp32.
// ===========================================================================

#define Bn 8
#define Cn 512
#define HIN 32
#define PIX 4096
#define XELEMS (Bn*Cn*PIX)
#define RGBELEMS (Bn*3*PIX)
#define PADHW 66
#define PADCELLS (PADHW*PADHW)

// smem layout (bytes from 1024-aligned base)
#define I_BUF   33792            // 4 rows * 66 cells * 128B (fp16)
#define W_BASE  67584            // 2 input buffers
#define W_STAGE 8192             // 64oc x 128B
#define DSMEM   (W_BASE + 3*W_STAGE)   // 92160

// ---------------- device scratch (allocation-free rule) -------------------
__device__ __half g_xa[(size_t)Bn*PADCELLS*Cn];
__device__ __half g_xb[(size_t)Bn*PADCELLS*Cn];
__device__ __half g_wt0[9*Cn*Cn];
__device__ __half g_wt1[9*Cn*Cn];
__device__ float g_s0[Bn*Cn], g_s1[Bn*Cn], g_s2[Bn*Cn];
__device__ float g_d0[Bn*Cn], g_d1[Bn*Cn];
__device__ float g_wsq0[Cn*Cn], g_wsq1[Cn*Cn];

// ---------------- helpers --------------------------------------------------
__device__ __forceinline__ uint32_t smem_u32(const void* p) {
    uint32_t a;
    asm("{ .reg .u64 t; cvta.to.shared.u64 t, %1; cvt.u32.u64 %0, t; }"
        : "=r"(a) : "l"(p));
    return a;
}
__device__ __forceinline__ void ldsm_x4(uint32_t* r, uint32_t addr) {
    asm volatile("ldmatrix.sync.aligned.m8n8.x4.shared.b16 {%0,%1,%2,%3}, [%4];"
        : "=r"(r[0]), "=r"(r[1]), "=r"(r[2]), "=r"(r[3]) : "r"(addr));
}
__device__ __forceinline__ void mma_f16(float* c, const uint32_t* a,
                                        const uint32_t* b) {
    asm volatile(
        "mma.sync.aligned.m16n8k16.row.col.f32.f16.f16.f32 "
        "{%0,%1,%2,%3},{%4,%5,%6,%7},{%8,%9},{%0,%1,%2,%3};"
        : "+f"(c[0]), "+f"(c[1]), "+f"(c[2]), "+f"(c[3])
        : "r"(a[0]), "r"(a[1]), "r"(a[2]), "r"(a[3]), "r"(b[0]), "r"(b[1]));
}
__device__ __forceinline__ void cp16(uint32_t dst, const void* src) {
    asm volatile("cp.async.cg.shared.global [%0], [%1], 16;"
        :: "r"(dst), "l"(src));
}
#define CP_COMMIT() asm volatile("cp.async.commit_group;" ::: "memory")
#define CP_WAIT1()  asm volatile("cp.async.wait_group 1;" ::: "memory")

// ---------------------------------------------------------------------------
// fused prep: styles (3 projections) + wsq + wprep + halo-zero
// ---------------------------------------------------------------------------
#define N_STY (3*Bn*Cn)            // 12288
#define N_WSQ (2*Cn*Cn)            // 524288
#define N_WPR (2*9*Cn*Cn)          // 4718592
#define N_ZER (Bn*260*256)         // 532480
#define N_PREP (N_STY + N_WSQ + N_WPR + N_ZER)

__global__ void k_prep(const float* __restrict__ w,
                       const float* __restrict__ sW0, const float* __restrict__ sB0,
                       const float* __restrict__ sW1, const float* __restrict__ sB1,
                       const float* __restrict__ sW2, const float* __restrict__ sB2,
                       const float* __restrict__ w0, const float* __restrict__ w1)
{
    int idx = blockIdx.x * blockDim.x + threadIdx.x;
    if (idx < N_STY) {
        int which = idx / (Bn * Cn);
        int rem   = idx % (Bn * Cn);
        int b = rem / Cn, c = rem % Cn;
        const float* sW = (which == 0) ? sW0 : (which == 1) ? sW1 : sW2;
        const float* sB = (which == 0) ? sB0 : (which == 1) ? sB1 : sB2;
        const float* wr = w + b * Cn;
        const float* sr = sW + c * Cn;
        float acc = 0.f;
        #pragma unroll 8
        for (int k = 0; k < Cn; ++k) acc += wr[k] * sr[k];
        acc += sB[c];
        ((which == 0) ? g_s0 : (which == 1) ? g_s1 : g_s2)[b * Cn + c] = acc;
        return;
    }
    idx -= N_STY;
    if (idx < N_WSQ) {
        const float* W = (idx < Cn * Cn) ? w0 : w1;
        float* out     = (idx < Cn * Cn) ? g_wsq0 : g_wsq1;
        int e = idx & (Cn * Cn - 1);
        const float* p = W + (size_t)e * 9;
        float a = 0.f;
        #pragma unroll
        for (int t = 0; t < 9; ++t) a += p[t] * p[t];
        out[e] = a;
        return;
    }
    idx -= N_WSQ;
    if (idx < N_WPR) {
        int layer = idx / (9 * Cn * Cn);
        int r = idx % (9 * Cn * Cn);
        int tap = r / (Cn * Cn);
        int rr = r % (Cn * Cn);
        int o = rr >> 9, i = rr & 511;
        const float* W = layer ? w1 : w0;
        float v = W[((size_t)o * Cn + i) * 9 + tap];
        size_t a = ((size_t)tap * Cn + o) * Cn + i;
        (layer ? g_wt1 : g_wt0)[a] = __float2half_rn(v);
        return;
    }
    idx -= N_WPR;
    if (idx < N_ZER) {
        int c2 = idx & 255;
        int cell = (idx >> 8) % 260;
        int b = (idx >> 8) / 260;
        int y, x;
        if (cell < 66)       { y = 0;  x = cell; }
        else if (cell < 132) { y = 65; x = cell - 66; }
        else { int r = cell - 132; y = 1 + (r & 63); x = (r >> 6) ? 65 : 0; }
        size_t a = ((((size_t)b * PADHW + y) * PADHW + x) * Cn) / 2 + c2;
        ((uint32_t*)g_xa)[a] = 0u;
        ((uint32_t*)g_xb)[a] = 0u;
    }
}

__global__ void k_demod()
{
    int idx = blockIdx.x * blockDim.x + threadIdx.x;
    if (idx >= 2 * Bn * Cn) return;
    int which = idx / (Bn * Cn);
    int rem   = idx % (Bn * Cn);
    int b = rem / Cn, o = rem % Cn;
    const float* wsq = which ? g_wsq1 : g_wsq0;
    const float* s   = which ? g_s1 : g_s0;
    const float* wr = wsq + o * Cn;
    const float* sr = s + b * Cn;
    float acc = 0.f;
    #pragma unroll 8
    for (int k = 0; k < Cn; ++k) { float sv = sr[k]; acc += wr[k] * sv * sv; }
    (which ? g_d1 : g_d0)[b * Cn + o] = rsqrtf(acc + 1e-8f);
}

// ---------------------------------------------------------------------------
// upsample maps 2x bilinear, *s0, write padded HWC fp16 plane
// ---------------------------------------------------------------------------
__global__ void __launch_bounds__(256) k_up(const float* __restrict__ maps)
{
    __shared__ unsigned short tile[64 * 65];
    int bx = blockIdx.x;
    int b = bx >> 6, y = bx & 63;
    int tid = threadIdx.x;

    int yl = (y - 1) >> 1, yu = yl + 1;
    float wyu = (y & 1) ? 0.25f : 0.75f;
    yl = max(yl, 0); yu = min(yu, HIN - 1);

    for (int c0 = 0; c0 < Cn; c0 += 64) {
        #pragma unroll
        for (int k = 0; k < 16; ++k) {
            int e = tid + (k << 8);
            int c = e >> 6, x = e & 63;
            int xl = (x - 1) >> 1, xu = xl + 1;
            float wxu = (x & 1) ? 0.25f : 0.75f;
            xl = max(xl, 0); xu = min(xu, HIN - 1);
            const float* p = maps + (size_t)(b * Cn + c0 + c) * (HIN * HIN);
            float v = (1.f - wyu) * ((1.f - wxu) * p[yl*HIN+xl] + wxu * p[yl*HIN+xu])
                    +         wyu * ((1.f - wxu) * p[yu*HIN+xl] + wxu * p[yu*HIN+xu]);
            v *= g_s0[b * Cn + c0 + c];
            tile[c * 65 + x] = __half_as_ushort(__float2half_rn(v));
        }
        __syncthreads();
        #pragma unroll
        for (int k = 0; k < 16; ++k) {
            int e = tid + (k << 8);
            int x = e >> 6, c = e & 63;
            size_t a = (((size_t)b * PADHW + y + 1) * PADHW + x + 1) * Cn + c0 + c;
            g_xa[a] = __ushort_as_half(tile[c * 65 + x]);
        }
        __syncthreads();
    }
}

// ---------------------------------------------------------------------------
// conv staging: weights (tap, 64ic) -> 64oc x 128B tile (512 cp16 segs)
// ---------------------------------------------------------------------------
__device__ __forceinline__ void stage_w(
    uint32_t wbase, int stg, const __half* __restrict__ wp,
    int o0, int tap, int ic0, int tid)
{
    const uint32_t base = wbase + stg * W_STAGE;
    #pragma unroll
    for (int k = 0; k < 2; ++k) {
        int s = tid + (k << 8);
        int r = s >> 3, g = s & 7;
        const __half* src = wp + ((size_t)tap * Cn + o0 + r) * Cn + ic0 + g * 8;
        uint32_t off = (uint32_t)((r << 7) + (g << 4));
        off ^= (off >> 3) & 0x70;
        cp16(base + off, src);
    }
}

// input band: 4 rows x 66 cells x 64 ic fp16 = 2112 cp16 segs, in 8 parts
__device__ __forceinline__ void stage_input_part(
    uint32_t ibase, int buf, int part,
    const __half* __restrict__ x, int b, int y0, int ic0, int tid)
{
    for (int t = tid; t < 264; t += 256) {
        int idx = part * 264 + t;
        int cell = idx >> 3, g = idx & 7;
        int r = cell / 66, xx = cell - r * 66;
        const __half* src = x
            + (((size_t)b * PADHW + y0 + r) * PADHW + xx) * Cn + ic0 + g * 8;
        uint32_t off = (uint32_t)((cell << 7) + (g << 4));
        off ^= (off >> 3) & 0x70;
        cp16(ibase + buf * I_BUF + off, src);
    }
}

// ---------------------------------------------------------------------------
// conv: D[64 oc, 128 px(2 rows)], 256 threads, warps 2(m) x 4(n),
// warp 32oc x 32px, 1 fp16 MMA per k-step, 3-stage weight ring (wait 1).
// ---------------------------------------------------------------------------
template<int EPI>
__global__ void __launch_bounds__(256) k_conv(
    const __half* __restrict__ xin,
    const __half* __restrict__ wp,
    const float* __restrict__ dmod,
    const float* __restrict__ bias,
    const float* __restrict__ nsc,
    const float* __restrict__ noise,
    const float* __restrict__ post,
    __half* __restrict__ outHp,
    float* __restrict__ outF)
{
    extern __shared__ __align__(16) char dsm_raw[];
    char* dbase = (char*)(((uintptr_t)dsm_raw + 1023) & ~(uintptr_t)1023);
    const uint32_t ib = smem_u32(dbase);
    const uint32_t wb = ib + W_BASE;
    const int tid = threadIdx.x;
    const int lane = tid & 31, wid = tid >> 5;
    const int mw = wid >> 2, nw = wid & 3;
    const int nt = blockIdx.x;
    const int o0 = blockIdx.y * 64;
    const int b  = nt >> 5;
    const int y0 = (nt & 31) * 2;

    float acc[2][4][4] = {};

    const int a_row = lane & 15;
    const int a_chalf = (lane >> 4) << 4;
    const int xl = ((lane >> 4) << 3) + (lane & 7);
    const int khalf = ((lane >> 3) & 1) << 4;
    const int xbase = (nw & 1) * 32 + xl;
    const int dyw = nw >> 1;

    // prologue: group A = full input band chunk0 + weights step0; group B = weights step1
    #pragma unroll
    for (int p = 0; p < 8; ++p)
        stage_input_part(ib, 0, p, xin, b, y0, 0, tid);
    stage_w(wb, 0, wp, o0, 0, 0, tid);
    CP_COMMIT();
    stage_w(wb, 1, wp, o0, 1, 0, tid);
    CP_COMMIT();

    int step = 0;
    for (int ic = 0; ic < 8; ++ic) {
        const int ibuf = ic & 1;
        const uint32_t ibb = ib + ibuf * I_BUF;
        for (int tap = 0; tap < 9; ++tap, ++step) {
            CP_WAIT1();
            __syncthreads();
            int ns = step + 2;
            if (ns < 72) {
                int nstg = ns - (ns / 3) * 3;     // ns % 3
                stage_w(wb, nstg, wp, o0, ns % 9, (ns / 9) << 6, tid);
            }
            if (tap < 8 && ic < 7)
                stage_input_part(ib, ibuf ^ 1, tap, xin, b, y0,
                                 (ic + 1) << 6, tid);
            CP_COMMIT();

            const int ky = tap / 3, kx = tap - ky * 3;
            const int cellbase = (dyw + ky) * 66 + xbase + kx;
            const int stg = step - (step / 3) * 3;
            const uint32_t ws = wb + stg * W_STAGE;

            #pragma unroll
            for (int ks = 0; ks < 4; ++ks) {
                uint32_t ah[2][4];
                #pragma unroll
                for (int sm = 0; sm < 2; ++sm) {
                    uint32_t off = (uint32_t)((mw*32 + sm*16 + a_row)*128
                                              + ks*32 + a_chalf);
                    off ^= (off >> 3) & 0x70;
                    ldsm_x4(ah[sm], ws + off);
                }
                #pragma unroll
                for (int half = 0; half < 2; ++half) {
                    uint32_t bh[4];
                    uint32_t off = (uint32_t)((cellbase + half*16)*128
                                              + ks*32 + khalf);
                    off ^= (off >> 3) & 0x70;
                    ldsm_x4(bh, ibb + off);
                    #pragma unroll
                    for (int sm = 0; sm < 2; ++sm)
                        #pragma unroll
                        for (int j = 0; j < 2; ++j)
                            mma_f16(acc[sm][half*2 + j], ah[sm], &bh[j*2]);
                }
            }
        }
    }

    // ---- epilogue. c-frag: e0,e1=(row, col,col+1) e2,e3=(row+8, ..)
    const int groupM = lane >> 2;
    const int groupN = 2 * (lane & 3);
    const float* np = noise + (size_t)b * PIX + y0 * 64;

    if (EPI == 0) {
        __syncthreads();
        uint32_t* tp = (uint32_t*)dbase;      // [64 px-pairs][68] u32
        #pragma unroll
        for (int sm = 0; sm < 2; ++sm) {
            #pragma unroll
            for (int ro = 0; ro < 2; ++ro) {
                int ocl = mw * 32 + sm * 16 + groupM + ro * 8;
                int oc = o0 + ocl;
                float d  = dmod[b * Cn + oc];
                float bi = bias[oc];
                float nv = nsc[oc];
                float ps = post[b * Cn + oc];
                #pragma unroll
                for (int sn = 0; sn < 4; ++sn) {
                    int px = nw * 32 + sn * 8 + groupN;
                    float v0 = acc[sm][sn][ro * 2 + 0] * d + bi + nv * np[px + 0];
                    float v1 = acc[sm][sn][ro * 2 + 1] * d + bi + nv * np[px + 1];
                    v0 = ((v0 >= 0.f) ? v0 : 0.2f * v0) * ps;
                    v1 = ((v1 >= 0.f) ? v1 : 0.2f * v1) * ps;
                    uint32_t pk = (uint32_t)__half_as_ushort(__float2half_rn(v0))
                        | ((uint32_t)__half_as_ushort(__float2half_rn(v1)) << 16);
                    tp[(px >> 1) * 68 + ocl] = pk;
                }
            }
        }
        __syncthreads();
        if (tid < 128) {
            int p = tid;
            int yy = y0 + (p >> 6), xx = p & 63;
            uint32_t sel = (p & 1) ? 0x7632u : 0x5410u;
            size_t abase = (((size_t)b * PADHW + yy + 1) * PADHW + xx + 1) * Cn + o0;
            uint4* dst = (uint4*)(outHp + abase);
            const uint32_t* srcp = tp + (p >> 1) * 68;
            #pragma unroll
            for (int i = 0; i < 8; ++i) {
                dst[i] = make_uint4(
                    __byte_perm(srcp[i*8+0], srcp[i*8+1], sel),
                    __byte_perm(srcp[i*8+2], srcp[i*8+3], sel),
                    __byte_perm(srcp[i*8+4], srcp[i*8+5], sel),
                    __byte_perm(srcp[i*8+6], srcp[i*8+7], sel));
            }
        }
    } else {
        #pragma unroll
        for (int sm = 0; sm < 2; ++sm) {
            #pragma unroll
            for (int ro = 0; ro < 2; ++ro) {
                int ocl = mw * 32 + sm * 16 + groupM + ro * 8;
                int oc = o0 + ocl;
                float d  = dmod[b * Cn + oc];
                float bi = bias[oc];
                float nv = nsc[oc];
                #pragma unroll
                for (int sn = 0; sn < 4; ++sn) {
                    int px = nw * 32 + sn * 8 + groupN;
                    float v0 = acc[sm][sn][ro * 2 + 0] * d + bi + nv * np[px + 0];
                    float v1 = acc[sm][sn][ro * 2 + 1] * d + bi + nv * np[px + 1];
                    v0 = (v0 >= 0.f) ? v0 : 0.2f * v0;
                    v1 = (v1 >= 0.f) ? v1 : 0.2f * v1;
                    int y = y0 + (px >> 6), x = px & 63;
                    float2* dp = (float2*)(outF + ((size_t)(b * Cn + oc) * 64 + y) * 64 + x);
                    *dp = make_float2(v0, v1);
                }
            }
        }
    }
}

// ---------------------------------------------------------------------------
// to_rgb: rgb_out = up2(rgb) + rgbB + (rgbW*s2) . x
// grid = Bn*64 (one row per block); thread = (x = tid&63, q = tid>>6).
// ---------------------------------------------------------------------------
__global__ void __launch_bounds__(256) k_rgb(
    const float* __restrict__ x,
    const float* __restrict__ rgb,
    const float* __restrict__ rgbW,
    const float* __restrict__ rgbB,
    float* __restrict__ outRGB)
{
    __shared__ float ws[3 * Cn];
    __shared__ float red[4][3][64];
    int b = blockIdx.x >> 6;
    int Y = blockIdx.x & 63;
    int tid = threadIdx.x;

    for (int idx = tid; idx < 3 * Cn; idx += 256)
        ws[idx] = rgbW[idx] * g_s2[b * Cn + (idx & (Cn - 1))];
    __syncthreads();

    int X = tid & 63;
    int q = tid >> 6;           // channel quarter

    const float* xp = x + (size_t)b * Cn * PIX + Y * 64 + X;
    float a0 = 0.f, a1 = 0.f, a2 = 0.f;
    int c0 = q * 128;
    #pragma unroll 8
    for (int i = 0; i < 128; ++i) {
        int c = c0 + i;
        float v = xp[(size_t)c * PIX];
        a0 += ws[c] * v;
        a1 += ws[Cn + c] * v;
        a2 += ws[2 * Cn + c] * v;
    }
    red[q][0][X] = a0;
    red[q][1][X] = a1;
    red[q][2][X] = a2;
    __syncthreads();

    if (tid < 64) {
        int yl = (Y - 1) >> 1; int yu = yl + 1;
        float wyu = (Y & 1) ? 0.25f : 0.75f;
        yl = max(yl, 0); yu = min(yu, HIN - 1);
        int xl = (X - 1) >> 1; int xu = xl + 1;
        float wxu = (X & 1) ? 0.25f : 0.75f;
        xl = max(xl, 0); xu = min(xu, HIN - 1);
        #pragma unroll
        for (int r = 0; r < 3; ++r) {
            float s = red[0][r][X] + red[1][r][X] + red[2][r][X] + red[3][r][X];
            const float* p = rgb + (size_t)(b * 3 + r) * (HIN * HIN);
            float up = (1.f - wyu) * ((1.f - wxu) * p[yl*HIN+xl] + wxu * p[yl*HIN+xu])
                     +         wyu * ((1.f - wxu) * p[yu*HIN+xl] + wxu * p[yu*HIN+xu]);
            outRGB[((size_t)(b * 3 + r) * 64 + Y) * 64 + X] = up + s + rgbB[r];
        }
    }
}

// ---------------------------------------------------------------------------
extern "C" void kernel_launch(void* const* d_in, const int* in_sizes, int n_in,
                              void* d_out, int out_size)
{
    const float* maps   = (const float*)d_in[0];
    const float* w      = (const float*)d_in[1];
    const float* rgb    = (const float*)d_in[2];
    const float* noise0 = (const float*)d_in[3];
    const float* noise1 = (const float*)d_in[4];
    const float* w0     = (const float*)d_in[5];
    const float* b0     = (const float*)d_in[6];
    const float* sW0    = (const float*)d_in[7];
    const float* sB0    = (const float*)d_in[8];
    const float* ns0    = (const float*)d_in[9];
    const float* w1     = (const float*)d_in[10];
    const float* b1     = (const float*)d_in[11];
    const float* sW1    = (const float*)d_in[12];
    const float* sB1    = (const float*)d_in[13];
    const float* ns1    = (const float*)d_in[14];
    const float* rgbW   = (const float*)d_in[15];
    const float* rgbB   = (const float*)d_in[16];
    const float* rgbSW  = (const float*)d_in[17];
    const float* rgbSB  = (const float*)d_in[18];

    float* out    = (float*)d_out;
    float* outRGB = out;
    float* outX   = out + RGBELEMS;

    __half *xa, *xb, *wt0, *wt1;
    float *d0p, *d1p, *s1p;
    cudaGetSymbolAddress((void**)&xa, g_xa);
    cudaGetSymbolAddress((void**)&xb, g_xb);
    cudaGetSymbolAddress((void**)&wt0, g_wt0);
    cudaGetSymbolAddress((void**)&wt1, g_wt1);
    cudaGetSymbolAddress((void**)&d0p, g_d0);
    cudaGetSymbolAddress((void**)&d1p, g_d1);
    cudaGetSymbolAddress((void**)&s1p, g_s1);

    const int DSM = 1024 + DSMEM;
    cudaFuncSetAttribute(k_conv<0>, cudaFuncAttributeMaxDynamicSharedMemorySize, DSM);
    cudaFuncSetAttribute(k_conv<1>, cudaFuncAttributeMaxDynamicSharedMemorySize, DSM);

    k_prep<<<(N_PREP + 255) / 256, 256>>>(w, sW0, sB0, sW1, sB1, rgbSW, rgbSB,
                                          w0, w1);
    k_demod<<<(2 * Bn * Cn + 255) / 256, 256>>>();
    k_up<<<Bn * 64, 256>>>(maps);

    dim3 gconv(256, 8);   // (b,ytile) x octile(64)
    k_conv<0><<<gconv, 256, DSM>>>(xa, wt0, d0p, b0, ns0, noise0,
                                   s1p, xb, nullptr);
    k_conv<1><<<gconv, 256, DSM>>>(xb, wt1, d1p, b1, ns1, noise1,
                                   nullptr, nullptr, outX);

    k_rgb<<<Bn * 64, 256>>>(outX, rgb, rgbW, rgbB, outRGB);
}

// round 10
// speedup vs baseline: 2.7149x; 1.0328x over previous
#include <cuda_runtime.h>
#include <cuda_fp16.h>
#include <cstdint>
#include <math.h>

// ===========================================================================
// StyleGAN2 block, convs via warp-level mma.sync fp16 (1 MMA/k-step).
// R10: CTA 64oc x 128px, 4 warps of 32oc x 64px (2m x 2n) -> 24 ldsm per
// CTA-k-step instead of 32; shared-pipe drops below tensor floor.
// Output: [rgb_out (8*3*64*64)] ++ [x (8*512*64*64)], fp32.
// ===========================================================================

#define Bn 8
#define Cn 512
#define HIN 32
#define PIX 4096
#define XELEMS (Bn*Cn*PIX)
#define RGBELEMS (Bn*3*PIX)
#define PADHW 66
#define PADCELLS (PADHW*PADHW)

// smem layout (bytes from 1024-aligned base)
#define I_BUF   33792            // 4 rows * 66 cells * 128B (fp16)
#define W_BASE  67584            // 2 input buffers
#define W_STAGE 8192             // 64oc x 128B
#define DSMEM   (W_BASE + 3*W_STAGE)   // 92160

// ---------------- device scratch (allocation-free rule) -------------------
__device__ __half g_xa[(size_t)Bn*PADCELLS*Cn];
__device__ __half g_xb[(size_t)Bn*PADCELLS*Cn];
__device__ __half g_wt0[9*Cn*Cn];
__device__ __half g_wt1[9*Cn*Cn];
__device__ float g_s0[Bn*Cn], g_s1[Bn*Cn], g_s2[Bn*Cn];
__device__ float g_d0[Bn*Cn], g_d1[Bn*Cn];
__device__ float g_wsq0[Cn*Cn], g_wsq1[Cn*Cn];

// ---------------- helpers --------------------------------------------------
__device__ __forceinline__ uint32_t smem_u32(const void* p) {
    uint32_t a;
    asm("{ .reg .u64 t; cvta.to.shared.u64 t, %1; cvt.u32.u64 %0, t; }"
        : "=r"(a) : "l"(p));
    return a;
}
__device__ __forceinline__ void ldsm_x4(uint32_t* r, uint32_t addr) {
    asm volatile("ldmatrix.sync.aligned.m8n8.x4.shared.b16 {%0,%1,%2,%3}, [%4];"
        : "=r"(r[0]), "=r"(r[1]), "=r"(r[2]), "=r"(r[3]) : "r"(addr));
}
__device__ __forceinline__ void mma_f16(float* c, const uint32_t* a,
                                        const uint32_t* b) {
    asm volatile(
        "mma.sync.aligned.m16n8k16.row.col.f32.f16.f16.f32 "
        "{%0,%1,%2,%3},{%4,%5,%6,%7},{%8,%9},{%0,%1,%2,%3};"
        : "+f"(c[0]), "+f"(c[1]), "+f"(c[2]), "+f"(c[3])
        : "r"(a[0]), "r"(a[1]), "r"(a[2]), "r"(a[3]), "r"(b[0]), "r"(b[1]));
}
__device__ __forceinline__ void cp16(uint32_t dst, const void* src) {
    asm volatile("cp.async.cg.shared.global [%0], [%1], 16;"
        :: "r"(dst), "l"(src));
}
#define CP_COMMIT() asm volatile("cp.async.commit_group;" ::: "memory")
#define CP_WAIT1()  asm volatile("cp.async.wait_group 1;" ::: "memory")

// ---------------------------------------------------------------------------
// fused prep: styles (3 projections) + wsq + wprep + halo-zero
// ---------------------------------------------------------------------------
#define N_STY (3*Bn*Cn)
#define N_WSQ (2*Cn*Cn)
#define N_WPR (2*9*Cn*Cn)
#define N_ZER (Bn*260*256)
#define N_PREP (N_STY + N_WSQ + N_WPR + N_ZER)

__global__ void k_prep(const float* __restrict__ w,
                       const float* __restrict__ sW0, const float* __restrict__ sB0,
                       const float* __restrict__ sW1, const float* __restrict__ sB1,
                       const float* __restrict__ sW2, const float* __restrict__ sB2,
                       const float* __restrict__ w0, const float* __restrict__ w1)
{
    int idx = blockIdx.x * blockDim.x + threadIdx.x;
    if (idx < N_STY) {
        int which = idx / (Bn * Cn);
        int rem   = idx % (Bn * Cn);
        int b = rem / Cn, c = rem % Cn;
        const float* sW = (which == 0) ? sW0 : (which == 1) ? sW1 : sW2;
        const float* sB = (which == 0) ? sB0 : (which == 1) ? sB1 : sB2;
        const float* wr = w + b * Cn;
        const float* sr = sW + c * Cn;
        float acc = 0.f;
        #pragma unroll 8
        for (int k = 0; k < Cn; ++k) acc += wr[k] * sr[k];
        acc += sB[c];
        ((which == 0) ? g_s0 : (which == 1) ? g_s1 : g_s2)[b * Cn + c] = acc;
        return;
    }
    idx -= N_STY;
    if (idx < N_WSQ) {
        const float* W = (idx < Cn * Cn) ? w0 : w1;
        float* out     = (idx < Cn * Cn) ? g_wsq0 : g_wsq1;
        int e = idx & (Cn * Cn - 1);
        const float* p = W + (size_t)e * 9;
        float a = 0.f;
        #pragma unroll
        for (int t = 0; t < 9; ++t) a += p[t] * p[t];
        out[e] = a;
        return;
    }
    idx -= N_WSQ;
    if (idx < N_WPR) {
        int layer = idx / (9 * Cn * Cn);
        int r = idx % (9 * Cn * Cn);
        int tap = r / (Cn * Cn);
        int rr = r % (Cn * Cn);
        int o = rr >> 9, i = rr & 511;
        const float* W = layer ? w1 : w0;
        float v = W[((size_t)o * Cn + i) * 9 + tap];
        size_t a = ((size_t)tap * Cn + o) * Cn + i;
        (layer ? g_wt1 : g_wt0)[a] = __float2half_rn(v);
        return;
    }
    idx -= N_WPR;
    if (idx < N_ZER) {
        int c2 = idx & 255;
        int cell = (idx >> 8) % 260;
        int b = (idx >> 8) / 260;
        int y, x;
        if (cell < 66)       { y = 0;  x = cell; }
        else if (cell < 132) { y = 65; x = cell - 66; }
        else { int r = cell - 132; y = 1 + (r & 63); x = (r >> 6) ? 65 : 0; }
        size_t a = ((((size_t)b * PADHW + y) * PADHW + x) * Cn) / 2 + c2;
        ((uint32_t*)g_xa)[a] = 0u;
        ((uint32_t*)g_xb)[a] = 0u;
    }
}

__global__ void k_demod()
{
    int idx = blockIdx.x * blockDim.x + threadIdx.x;
    if (idx >= 2 * Bn * Cn) return;
    int which = idx / (Bn * Cn);
    int rem   = idx % (Bn * Cn);
    int b = rem / Cn, o = rem % Cn;
    const float* wsq = which ? g_wsq1 : g_wsq0;
    const float* s   = which ? g_s1 : g_s0;
    const float* wr = wsq + o * Cn;
    const float* sr = s + b * Cn;
    float acc = 0.f;
    #pragma unroll 8
    for (int k = 0; k < Cn; ++k) { float sv = sr[k]; acc += wr[k] * sv * sv; }
    (which ? g_d1 : g_d0)[b * Cn + o] = rsqrtf(acc + 1e-8f);
}

// ---------------------------------------------------------------------------
// upsample maps 2x bilinear, *s0, write padded HWC fp16 plane
// ---------------------------------------------------------------------------
__global__ void __launch_bounds__(256) k_up(const float* __restrict__ maps)
{
    __shared__ unsigned short tile[64 * 65];
    int bx = blockIdx.x;
    int b = bx >> 6, y = bx & 63;
    int tid = threadIdx.x;

    int yl = (y - 1) >> 1, yu = yl + 1;
    float wyu = (y & 1) ? 0.25f : 0.75f;
    yl = max(yl, 0); yu = min(yu, HIN - 1);

    for (int c0 = 0; c0 < Cn; c0 += 64) {
        #pragma unroll
        for (int k = 0; k < 16; ++k) {
            int e = tid + (k << 8);
            int c = e >> 6, x = e & 63;
            int xl = (x - 1) >> 1, xu = xl + 1;
            float wxu = (x & 1) ? 0.25f : 0.75f;
            xl = max(xl, 0); xu = min(xu, HIN - 1);
            const float* p = maps + (size_t)(b * Cn + c0 + c) * (HIN * HIN);
            float v = (1.f - wyu) * ((1.f - wxu) * p[yl*HIN+xl] + wxu * p[yl*HIN+xu])
                    +         wyu * ((1.f - wxu) * p[yu*HIN+xl] + wxu * p[yu*HIN+xu]);
            v *= g_s0[b * Cn + c0 + c];
            tile[c * 65 + x] = __half_as_ushort(__float2half_rn(v));
        }
        __syncthreads();
        #pragma unroll
        for (int k = 0; k < 16; ++k) {
            int e = tid + (k << 8);
            int x = e >> 6, c = e & 63;
            size_t a = (((size_t)b * PADHW + y + 1) * PADHW + x + 1) * Cn + c0 + c;
            g_xa[a] = __ushort_as_half(tile[c * 65 + x]);
        }
        __syncthreads();
    }
}

// ---------------------------------------------------------------------------
// conv staging (128 threads)
// ---------------------------------------------------------------------------
__device__ __forceinline__ void stage_w(
    uint32_t wbase, int stg, const __half* __restrict__ wp,
    int o0, int tap, int ic0, int tid)
{
    const uint32_t base = wbase + stg * W_STAGE;
    #pragma unroll
    for (int k = 0; k < 4; ++k) {
        int s = tid + (k << 7);
        int r = s >> 3, g = s & 7;
        const __half* src = wp + ((size_t)tap * Cn + o0 + r) * Cn + ic0 + g * 8;
        uint32_t off = (uint32_t)((r << 7) + (g << 4));
        off ^= (off >> 3) & 0x70;
        cp16(base + off, src);
    }
}

// input band: 4 rows x 66 cells x 64 ic fp16 = 2112 cp16 segs, in 8 parts
__device__ __forceinline__ void stage_input_part(
    uint32_t ibase, int buf, int part,
    const __half* __restrict__ x, int b, int y0, int ic0, int tid)
{
    for (int t = tid; t < 264; t += 128) {
        int idx = part * 264 + t;
        int cell = idx >> 3, g = idx & 7;
        int r = cell / 66, xx = cell - r * 66;
        const __half* src = x
            + (((size_t)b * PADHW + y0 + r) * PADHW + xx) * Cn + ic0 + g * 8;
        uint32_t off = (uint32_t)((cell << 7) + (g << 4));
        off ^= (off >> 3) & 0x70;
        cp16(ibase + buf * I_BUF + off, src);
    }
}

// ---------------------------------------------------------------------------
// conv: D[64 oc, 128 px(2 rows)], 128 threads, 4 warps (2m x 2n),
// warp 32oc x 64px, 1 fp16 MMA per k-step, 3-stage weight ring (wait 1).
// ---------------------------------------------------------------------------
template<int EPI>
__global__ void __launch_bounds__(128) k_conv(
    const __half* __restrict__ xin,
    const __half* __restrict__ wp,
    const float* __restrict__ dmod,
    const float* __restrict__ bias,
    const float* __restrict__ nsc,
    const float* __restrict__ noise,
    const float* __restrict__ post,
    __half* __restrict__ outHp,
    float* __restrict__ outF)
{
    extern __shared__ __align__(16) char dsm_raw[];
    char* dbase = (char*)(((uintptr_t)dsm_raw + 1023) & ~(uintptr_t)1023);
    const uint32_t ib = smem_u32(dbase);
    const uint32_t wb = ib + W_BASE;
    const int tid = threadIdx.x;
    const int lane = tid & 31, wid = tid >> 5;      // 4 warps
    const int mw = wid >> 1, nwp = wid & 1;         // 2m x 2n
    const int nt = blockIdx.x;
    const int o0 = blockIdx.y * 64;
    const int b  = nt >> 5;
    const int y0 = (nt & 31) * 2;

    float acc[2][8][4] = {};    // [m-frag][n-frag(8px)][4]

    const int a_row = lane & 15;
    const int a_chalf = (lane >> 4) << 4;
    const int xl = ((lane >> 4) << 3) + (lane & 7);
    const int khalf = ((lane >> 3) & 1) << 4;

    // prologue
    #pragma unroll
    for (int p = 0; p < 8; ++p)
        stage_input_part(ib, 0, p, xin, b, y0, 0, tid);
    stage_w(wb, 0, wp, o0, 0, 0, tid);
    CP_COMMIT();
    stage_w(wb, 1, wp, o0, 1, 0, tid);
    CP_COMMIT();

    int step = 0;
    for (int ic = 0; ic < 8; ++ic) {
        const int ibuf = ic & 1;
        const uint32_t ibb = ib + ibuf * I_BUF;
        for (int tap = 0; tap < 9; ++tap, ++step) {
            CP_WAIT1();
            __syncthreads();
            int ns = step + 2;
            if (ns < 72) {
                int nstg = ns - (ns / 3) * 3;
                stage_w(wb, nstg, wp, o0, ns % 9, (ns / 9) << 6, tid);
            }
            if (tap < 8 && ic < 7)
                stage_input_part(ib, ibuf ^ 1, tap, xin, b, y0,
                                 (ic + 1) << 6, tid);
            CP_COMMIT();

            const int ky = tap / 3, kx = tap - ky * 3;
            const int cellrow = (nwp + ky) * 66 + kx + xl;
            const int stg = step - (step / 3) * 3;
            const uint32_t ws = wb + stg * W_STAGE;

            #pragma unroll
            for (int ks = 0; ks < 4; ++ks) {
                uint32_t ah[2][4];
                #pragma unroll
                for (int sm = 0; sm < 2; ++sm) {
                    uint32_t off = (uint32_t)((mw*32 + sm*16 + a_row)*128
                                              + ks*32 + a_chalf);
                    off ^= (off >> 3) & 0x70;
                    ldsm_x4(ah[sm], ws + off);
                }
                uint32_t bh[4][4];
                #pragma unroll
                for (int sp = 0; sp < 4; ++sp) {
                    uint32_t off = (uint32_t)((cellrow + sp*16)*128
                                              + ks*32 + khalf);
                    off ^= (off >> 3) & 0x70;
                    ldsm_x4(bh[sp], ibb + off);
                }
                #pragma unroll
                for (int sm = 0; sm < 2; ++sm)
                    #pragma unroll
                    for (int sp = 0; sp < 4; ++sp)
                        #pragma unroll
                        for (int j = 0; j < 2; ++j)
                            mma_f16(acc[sm][sp*2 + j], ah[sm], &bh[sp][j*2]);
            }
        }
    }

    // ---- epilogue. c-frag: e0,e1=(row, col,col+1) e2,e3=(row+8, ..)
    const int groupM = lane >> 2;
    const int groupN = 2 * (lane & 3);
    const float* np = noise + (size_t)b * PIX + y0 * 64;

    if (EPI == 0) {
        __syncthreads();
        uint32_t* tp = (uint32_t*)dbase;      // [64 px-pairs][68] u32
        #pragma unroll
        for (int sm = 0; sm < 2; ++sm) {
            #pragma unroll
            for (int ro = 0; ro < 2; ++ro) {
                int ocl = mw * 32 + sm * 16 + groupM + ro * 8;
                int oc = o0 + ocl;
                float d  = dmod[b * Cn + oc];
                float bi = bias[oc];
                float nv = nsc[oc];
                float ps = post[b * Cn + oc];
                #pragma unroll
                for (int sn = 0; sn < 8; ++sn) {
                    int px = nwp * 64 + sn * 8 + groupN;
                    float v0 = acc[sm][sn][ro * 2 + 0] * d + bi + nv * np[px + 0];
                    float v1 = acc[sm][sn][ro * 2 + 1] * d + bi + nv * np[px + 1];
                    v0 = ((v0 >= 0.f) ? v0 : 0.2f * v0) * ps;
                    v1 = ((v1 >= 0.f) ? v1 : 0.2f * v1) * ps;
                    uint32_t pk = (uint32_t)__half_as_ushort(__float2half_rn(v0))
                        | ((uint32_t)__half_as_ushort(__float2half_rn(v1)) << 16);
                    tp[(px >> 1) * 68 + ocl] = pk;
                }
            }
        }
        __syncthreads();
        {
            int p = tid;
            int yy = y0 + (p >> 6), xx = p & 63;
            uint32_t sel = (p & 1) ? 0x7632u : 0x5410u;
            size_t abase = (((size_t)b * PADHW + yy + 1) * PADHW + xx + 1) * Cn + o0;
            uint4* dst = (uint4*)(outHp + abase);
            const uint32_t* srcp = tp + (p >> 1) * 68;
            #pragma unroll
            for (int i = 0; i < 8; ++i) {
                dst[i] = make_uint4(
                    __byte_perm(srcp[i*8+0], srcp[i*8+1], sel),
                    __byte_perm(srcp[i*8+2], srcp[i*8+3], sel),
                    __byte_perm(srcp[i*8+4], srcp[i*8+5], sel),
                    __byte_perm(srcp[i*8+6], srcp[i*8+7], sel));
            }
        }
    } else {
        const int yrow = y0 + nwp;
        #pragma unroll
        for (int sm = 0; sm < 2; ++sm) {
            #pragma unroll
            for (int ro = 0; ro < 2; ++ro) {
                int ocl = mw * 32 + sm * 16 + groupM + ro * 8;
                int oc = o0 + ocl;
                float d  = dmod[b * Cn + oc];
                float bi = bias[oc];
                float nv = nsc[oc];
                float* dst = outF + ((size_t)(b * Cn + oc) * 64 + yrow) * 64;
                #pragma unroll
                for (int sn = 0; sn < 8; ++sn) {
                    int x = sn * 8 + groupN;
                    int px = nwp * 64 + x;
                    float v0 = acc[sm][sn][ro * 2 + 0] * d + bi + nv * np[px + 0];
                    float v1 = acc[sm][sn][ro * 2 + 1] * d + bi + nv * np[px + 1];
                    v0 = (v0 >= 0.f) ? v0 : 0.2f * v0;
                    v1 = (v1 >= 0.f) ? v1 : 0.2f * v1;
                    *(float2*)(dst + x) = make_float2(v0, v1);
                }
            }
        }
    }
}

// ---------------------------------------------------------------------------
// to_rgb: rgb_out = up2(rgb) + rgbB + (rgbW*s2) . x
// ---------------------------------------------------------------------------
__global__ void __launch_bounds__(256) k_rgb(
    const float* __restrict__ x,
    const float* __restrict__ rgb,
    const float* __restrict__ rgbW,
    const float* __restrict__ rgbB,
    float* __restrict__ outRGB)
{
    __shared__ float ws[3 * Cn];
    __shared__ float red[4][3][64];
    int b = blockIdx.x >> 6;
    int Y = blockIdx.x & 63;
    int tid = threadIdx.x;

    for (int idx = tid; idx < 3 * Cn; idx += 256)
        ws[idx] = rgbW[idx] * g_s2[b * Cn + (idx & (Cn - 1))];
    __syncthreads();

    int X = tid & 63;
    int q = tid >> 6;

    const float* xp = x + (size_t)b * Cn * PIX + Y * 64 + X;
    float a0 = 0.f, a1 = 0.f, a2 = 0.f;
    int c0 = q * 128;
    #pragma unroll 8
    for (int i = 0; i < 128; ++i) {
        int c = c0 + i;
        float v = xp[(size_t)c * PIX];
        a0 += ws[c] * v;
        a1 += ws[Cn + c] * v;
        a2 += ws[2 * Cn + c] * v;
    }
    red[q][0][X] = a0;
    red[q][1][X] = a1;
    red[q][2][X] = a2;
    __syncthreads();

    if (tid < 64) {
        int yl = (Y - 1) >> 1; int yu = yl + 1;
        float wyu = (Y & 1) ? 0.25f : 0.75f;
        yl = max(yl, 0); yu = min(yu, HIN - 1);
        int xl = (X - 1) >> 1; int xu = xl + 1;
        float wxu = (X & 1) ? 0.25f : 0.75f;
        xl = max(xl, 0); xu = min(xu, HIN - 1);
        #pragma unroll
        for (int r = 0; r < 3; ++r) {
            float s = red[0][r][X] + red[1][r][X] + red[2][r][X] + red[3][r][X];
            const float* p = rgb + (size_t)(b * 3 + r) * (HIN * HIN);
            float up = (1.f - wyu) * ((1.f - wxu) * p[yl*HIN+xl] + wxu * p[yl*HIN+xu])
                     +         wyu * ((1.f - wxu) * p[yu*HIN+xl] + wxu * p[yu*HIN+xu]);
            outRGB[((size_t)(b * 3 + r) * 64 + Y) * 64 + X] = up + s + rgbB[r];
        }
    }
}

// ---------------------------------------------------------------------------
extern "C" void kernel_launch(void* const* d_in, const int* in_sizes, int n_in,
                              void* d_out, int out_size)
{
    const float* maps   = (const float*)d_in[0];
    const float* w      = (const float*)d_in[1];
    const float* rgb    = (const float*)d_in[2];
    const float* noise0 = (const float*)d_in[3];
    const float* noise1 = (const float*)d_in[4];
    const float* w0     = (const float*)d_in[5];
    const float* b0     = (const float*)d_in[6];
    const float* sW0    = (const float*)d_in[7];
    const float* sB0    = (const float*)d_in[8];
    const float* ns0    = (const float*)d_in[9];
    const float* w1     = (const float*)d_in[10];
    const float* b1     = (const float*)d_in[11];
    const float* sW1    = (const float*)d_in[12];
    const float* sB1    = (const float*)d_in[13];
    const float* ns1    = (const float*)d_in[14];
    const float* rgbW   = (const float*)d_in[15];
    const float* rgbB   = (const float*)d_in[16];
    const float* rgbSW  = (const float*)d_in[17];
    const float* rgbSB  = (const float*)d_in[18];

    float* out    = (float*)d_out;
    float* outRGB = out;
    float* outX   = out + RGBELEMS;

    __half *xa, *xb, *wt0, *wt1;
    float *d0p, *d1p, *s1p;
    cudaGetSymbolAddress((void**)&xa, g_xa);
    cudaGetSymbolAddress((void**)&xb, g_xb);
    cudaGetSymbolAddress((void**)&wt0, g_wt0);
    cudaGetSymbolAddress((void**)&wt1, g_wt1);
    cudaGetSymbolAddress((void**)&d0p, g_d0);
    cudaGetSymbolAddress((void**)&d1p, g_d1);
    cudaGetSymbolAddress((void**)&s1p, g_s1);

    const int DSM = 1024 + DSMEM;
    cudaFuncSetAttribute(k_conv<0>, cudaFuncAttributeMaxDynamicSharedMemorySize, DSM);
    cudaFuncSetAttribute(k_conv<1>, cudaFuncAttributeMaxDynamicSharedMemorySize, DSM);

    k_prep<<<(N_PREP + 255) / 256, 256>>>(w, sW0, sB0, sW1, sB1, rgbSW, rgbSB,
                                          w0, w1);
    k_demod<<<(2 * Bn * Cn + 255) / 256, 256>>>();
    k_up<<<Bn * 64, 256>>>(maps);

    dim3 gconv(256, 8);   // (b,ytile) x octile(64)
    k_conv<0><<<gconv, 128, DSM>>>(xa, wt0, d0p, b0, ns0, noise0,
                                   s1p, xb, nullptr);
    k_conv<1><<<gconv, 128, DSM>>>(xb, wt1, d1p, b1, ns1, noise1,
                                   nullptr, nullptr, outX);

    k_rgb<<<Bn * 64, 256>>>(outX, rgb, rgbW, rgbB, outRGB);
}